// round 12
// baseline (speedup 1.0000x reference)
#include <cuda_runtime.h>
#include <cuda_bf16.h>
#include <math.h>
#include <stdint.h>

// ---------------------------------------------------------------------------
// Problem constants
// ---------------------------------------------------------------------------
#define BATCH   2
#define SEQ     2048
#define EMBED   3584
#define NH      16
#define NKV     8
#define HDIM    256
#define MROWS   (BATCH*SEQ)          // 4096
#define QCOLS   (NH*HDIM)            // 4096
#define KCOLS   (NKV*HDIM)           // 2048
#define NPACK   (QCOLS + 2*KCOLS)    // 8192 packed QKV columns
#define WINDOW  1024

// ---------------------------------------------------------------------------
// Static device scratch (no cudaMalloc allowed)
// ---------------------------------------------------------------------------
__device__ float g_V  [(size_t)MROWS*KCOLS];
__device__ float g_cos[SEQ*(HDIM/2)];
__device__ float g_sin[SEQ*(HDIM/2)];

// bf16 hi/lo splits
__device__ __nv_bfloat16 g_Hh [(size_t)MROWS*EMBED];
__device__ __nv_bfloat16 g_Hl [(size_t)MROWS*EMBED];
__device__ __nv_bfloat16 g_WpH[(size_t)NPACK*EMBED];   // packed Wq|Wk|Wv, transposed+split
__device__ __nv_bfloat16 g_WpL[(size_t)NPACK*EMBED];
__device__ __nv_bfloat16 g_WotH[(size_t)EMBED*QCOLS];
__device__ __nv_bfloat16 g_WotL[(size_t)EMBED*QCOLS];
__device__ __nv_bfloat16 g_Ch  [(size_t)MROWS*QCOLS];
__device__ __nv_bfloat16 g_Cl  [(size_t)MROWS*QCOLS];

// attention operands (bf16 splits)
__device__ __nv_bfloat16 g_Qh [(size_t)MROWS*QCOLS];
__device__ __nv_bfloat16 g_Ql [(size_t)MROWS*QCOLS];
__device__ __nv_bfloat16 g_Kh [(size_t)MROWS*KCOLS];
__device__ __nv_bfloat16 g_Kl [(size_t)MROWS*KCOLS];
__device__ __nv_bfloat16 g_VtH[(size_t)MROWS*KCOLS];   // per-batch transposed [KCOLS][SEQ]
__device__ __nv_bfloat16 g_VtL[(size_t)MROWS*KCOLS];

// ---------------------------------------------------------------------------
// PTX helpers (sm_100-safe: no tcgen05, no clusters)
// ---------------------------------------------------------------------------
__device__ __forceinline__ uint32_t smem_u32(const void* p) {
    uint32_t a;
    asm("{ .reg .u64 t; cvta.to.shared.u64 t, %1; cvt.u32.u64 %0, t; }" : "=r"(a) : "l"(p));
    return a;
}
__device__ __forceinline__ void cp16(uint32_t dst, const void* src) {
    asm volatile("cp.async.cg.shared.global [%0], [%1], 16;" :: "r"(dst), "l"(src) : "memory");
}
__device__ __forceinline__ void ldmx4(uint32_t* r, uint32_t addr) {
    asm volatile("ldmatrix.sync.aligned.m8n8.x4.shared.b16 {%0,%1,%2,%3}, [%4];"
                 : "=r"(r[0]), "=r"(r[1]), "=r"(r[2]), "=r"(r[3]) : "r"(addr));
}
__device__ __forceinline__ void mma_bf16(float* c, const uint32_t* a,
                                         uint32_t b0, uint32_t b1) {
    asm volatile(
        "mma.sync.aligned.m16n8k16.row.col.f32.bf16.bf16.f32 "
        "{%0,%1,%2,%3}, {%4,%5,%6,%7}, {%8,%9}, {%0,%1,%2,%3};"
        : "+f"(c[0]), "+f"(c[1]), "+f"(c[2]), "+f"(c[3])
        : "r"(a[0]), "r"(a[1]), "r"(a[2]), "r"(a[3]), "r"(b0), "r"(b1));
}

// FMA-pipe exp (no MUFU): e^x for |x| <= ~85, rel err ~1.5e-7
__device__ __forceinline__ float fexp(float x) {
    float y  = x * 1.4426950408889634f;          // log2(e)
    float fm = y + 12582912.0f;                  // round-to-nearest via magic
    float nf = fm - 12582912.0f;
    float f  = y - nf;                           // [-0.5, 0.5]
    int   sc = ((__float_as_int(fm) - 0x4B400000) + 127) << 23;
    float t  = f * 0.6931471805599453f;
    float p  = 1.0f + t*(1.0f + t*(0.5f + t*(0.16666667f +
               t*(0.041666667f + t*(0.008333334f + t*0.0013888889f)))));
    return p * __int_as_float(sc);
}
// FMA-pipe reciprocal (bit-hack + 3 Newton)
__device__ __forceinline__ float frcp(float d) {
    float r = __int_as_float(0x7EF311C3 - __float_as_int(d));
    r = r * (2.0f - d * r);
    r = r * (2.0f - d * r);
    r = r * (2.0f - d * r);
    return r;
}

// ---------------------------------------------------------------------------
// fp32 -> bf16 hi/lo split (vectorized)
// ---------------------------------------------------------------------------
__global__ void split_kernel(const float* __restrict__ in,
                             __nv_bfloat16* __restrict__ hi,
                             __nv_bfloat16* __restrict__ lo, int n4)
{
    int i = blockIdx.x * 256 + threadIdx.x;
    if (i >= n4) return;
    float4 v = ((const float4*)in)[i];
    __nv_bfloat16 h0 = __float2bfloat16(v.x);
    __nv_bfloat16 h1 = __float2bfloat16(v.y);
    __nv_bfloat16 h2 = __float2bfloat16(v.z);
    __nv_bfloat16 h3 = __float2bfloat16(v.w);
    __nv_bfloat16 l0 = __float2bfloat16(v.x - __bfloat162float(h0));
    __nv_bfloat16 l1 = __float2bfloat16(v.y - __bfloat162float(h1));
    __nv_bfloat16 l2 = __float2bfloat16(v.z - __bfloat162float(h2));
    __nv_bfloat16 l3 = __float2bfloat16(v.w - __bfloat162float(h3));
    ((__nv_bfloat162*)hi)[2*i]   = __halves2bfloat162(h0, h1);
    ((__nv_bfloat162*)hi)[2*i+1] = __halves2bfloat162(h2, h3);
    ((__nv_bfloat162*)lo)[2*i]   = __halves2bfloat162(l0, l1);
    ((__nv_bfloat162*)lo)[2*i+1] = __halves2bfloat162(l2, l3);
}

// ---------------------------------------------------------------------------
// Transpose + split: W [K,N] fp32 -> Th/Tl rows [rowoff + perm(n)][K] bf16.
// perm=1 interleaves RoPE pairs: col i<128 -> 2i, col i>=128 -> 2(i-128)+1
// (within each 256-wide head block) so GEMM output pairs are adjacent.
// ---------------------------------------------------------------------------
__global__ void tsplit_kernel(const float* __restrict__ W,
                              __nv_bfloat16* __restrict__ Th,
                              __nv_bfloat16* __restrict__ Tl, int K, int N,
                              int perm, int rowoff)
{
    __shared__ float t[32][33];
    int n0 = blockIdx.x * 32, k0 = blockIdx.y * 32;
    int tx = threadIdx.x, ty = threadIdx.y;
#pragma unroll
    for (int i = 0; i < 32; i += 8)
        t[ty + i][tx] = W[(size_t)(k0 + ty + i) * N + n0 + tx];
    __syncthreads();
#pragma unroll
    for (int i = 0; i < 32; i += 8) {
        float v = t[tx][ty + i];
        __nv_bfloat16 h = __float2bfloat16(v);
        __nv_bfloat16 l = __float2bfloat16(v - __bfloat162float(h));
        int n = n0 + ty + i;
        int nb = n & 255;
        int np = perm ? ((n & ~255) + ((nb < 128) ? (nb << 1) : (((nb - 128) << 1) | 1)))
                      : n;
        size_t o = (size_t)(rowoff + np) * K + k0 + tx;
        Th[o] = h;
        Tl[o] = l;
    }
}

// ---------------------------------------------------------------------------
// V transpose+split per batch: g_V [b*SEQ+s][KCOLS] -> Vt [b][KCOLS][SEQ]
// ---------------------------------------------------------------------------
__global__ void vtsplit_kernel(const float* __restrict__ V,
                               __nv_bfloat16* __restrict__ Th,
                               __nv_bfloat16* __restrict__ Tl)
{
    __shared__ float t[32][33];
    int s0 = blockIdx.x * 32, c0 = blockIdx.y * 32, b = blockIdx.z;
    int tx = threadIdx.x, ty = threadIdx.y;
#pragma unroll
    for (int i = 0; i < 32; i += 8)
        t[ty + i][tx] = V[((size_t)b * SEQ + s0 + ty + i) * KCOLS + c0 + tx];
    __syncthreads();
#pragma unroll
    for (int i = 0; i < 32; i += 8) {
        float v = t[tx][ty + i];
        __nv_bfloat16 h = __float2bfloat16(v);
        __nv_bfloat16 l = __float2bfloat16(v - __bfloat162float(h));
        size_t o = ((size_t)b * KCOLS + c0 + ty + i) * SEQ + s0 + tx;
        Th[o] = h;
        Tl[o] = l;
    }
}

// ---------------------------------------------------------------------------
// RoPE tables (double precision)
// ---------------------------------------------------------------------------
__global__ void rope_tables_kernel()
{
    int idx = blockIdx.x * 256 + threadIdx.x;
    if (idx >= SEQ * (HDIM / 2)) return;
    int i = idx & 127;
    int pos = idx >> 7;
    double invf = pow(10000.0, -(double)(2 * i) / (double)HDIM);
    double ang = (double)pos * invf;
    g_cos[idx] = (float)cos(ang);
    g_sin[idx] = (float)sin(ang);
}

// ---------------------------------------------------------------------------
// mma.sync bf16x3 GEMM: 2-stage pipeline, 2 CTAs/SM, B-resident term order
// (Ah loaded once serves Ah*Bh and Ah*Bl; Bh stays resident for Al*Bh:
//  12 ldmatrix.x4 per warp per k-slice instead of 16).
// mode 0: C[M,N] fp32 plain.
// mode 1: fused QKV: RoPE epilogue -> Qh/Ql/Kh/Kl; V segment -> Vb fp32.
// ---------------------------------------------------------------------------
#define GKC       32
#define GSTRIDE   40
#define GTILE_B   (128*GSTRIDE*2)    // 10240 B per tile
#define GSTAGE_B  (4*GTILE_B)        // Ah, Al, Bh, Bl = 40960 B
#define GEMM_SMEM (2*GSTAGE_B)       // 81920 B -> 2 CTAs/SM

__device__ __forceinline__ void fill_stage(uint32_t stb,
                                           const __nv_bfloat16* Ah0,
                                           const __nv_bfloat16* Al0,
                                           const __nv_bfloat16* Bh0,
                                           const __nv_bfloat16* Bl0,
                                           int K, int tid)
{
    const __nv_bfloat16* srcs[4] = {Ah0, Al0, Bh0, Bl0};
#pragma unroll
    for (int t = 0; t < 4; t++) {
        uint32_t tb = stb + t * GTILE_B;
        const char* s = (const char*)srcs[t];
#pragma unroll
        for (int i = 0; i < 2; i++) {
            int id = tid + i * 256;
            int row = id >> 2, ch = id & 3;
            cp16(tb + row * (GSTRIDE * 2) + ch * 16,
                 s + (size_t)row * K * 2 + ch * 16);
        }
    }
    asm volatile("cp.async.commit_group;" ::: "memory");
}

__global__ void __launch_bounds__(256, 2)
gemm_mma_kernel(const __nv_bfloat16* __restrict__ Ah,
                const __nv_bfloat16* __restrict__ Al,
                const __nv_bfloat16* __restrict__ Bh,
                const __nv_bfloat16* __restrict__ Bl,
                float* __restrict__ C, int M, int N, int K,
                int fused,
                __nv_bfloat16* __restrict__ Qh, __nv_bfloat16* __restrict__ Ql,
                __nv_bfloat16* __restrict__ Kh, __nv_bfloat16* __restrict__ Kl,
                float* __restrict__ Vb)
{
    extern __shared__ char gsm[];
    const uint32_t sbase = smem_u32(gsm);
    const int tid = threadIdx.x;
    const int wid = tid >> 5, lane = tid & 31;
    const int wm = wid & 1, wn = wid >> 1;
    const int m0 = blockIdx.y * 128, n0 = blockIdx.x * 128;

    uint32_t a_off[4], b_off[2];
#pragma unroll
    for (int mt = 0; mt < 4; mt++)
        a_off[mt] = ((wm * 64 + mt * 16 + (lane & 15)) * GSTRIDE
                     + (lane >> 4) * 8) * 2;
#pragma unroll
    for (int np = 0; np < 2; np++)
        b_off[np] = ((wn * 32 + np * 16 + (lane & 7) + ((lane >> 4) & 1) * 8) * GSTRIDE
                     + ((lane >> 3) & 1) * 8) * 2;

    const __nv_bfloat16* Ah0 = Ah + (size_t)m0 * K;
    const __nv_bfloat16* Al0 = Al + (size_t)m0 * K;
    const __nv_bfloat16* Bh0 = Bh + (size_t)n0 * K;
    const __nv_bfloat16* Bl0 = Bl + (size_t)n0 * K;

    float acc[4][4][4];
#pragma unroll
    for (int mt = 0; mt < 4; mt++)
#pragma unroll
        for (int nt = 0; nt < 4; nt++)
#pragma unroll
            for (int r = 0; r < 4; r++) acc[mt][nt][r] = 0.f;

    const int NC = K / GKC;

    // prologue: 2 stages in flight
#pragma unroll
    for (int c = 0; c < 2; c++)
        fill_stage(sbase + c * GSTAGE_B, Ah0 + c * GKC, Al0 + c * GKC,
                   Bh0 + c * GKC, Bl0 + c * GKC, K, tid);

    for (int c = 0; c < NC; c++) {
        const uint32_t stb = sbase + (c & 1) * GSTAGE_B;
        asm volatile("cp.async.wait_group %0;" :: "n"(1) : "memory");
        __syncthreads();

#pragma unroll
        for (int ks = 0; ks < 2; ks++) {
            const uint32_t ko = ks * 32;
            uint32_t ax[4][4], bh[2][4], bl[2][4];

            // load Ah + both B splits (B stays resident for all 3 terms)
#pragma unroll
            for (int mt = 0; mt < 4; mt++) ldmx4(ax[mt], stb + 0 * GTILE_B + a_off[mt] + ko);
#pragma unroll
            for (int np = 0; np < 2; np++) {
                ldmx4(bh[np], stb + 2 * GTILE_B + b_off[np] + ko);
                ldmx4(bl[np], stb + 3 * GTILE_B + b_off[np] + ko);
            }

            // ---- term 1: Ah * Bh ----
#pragma unroll
            for (int mt = 0; mt < 4; mt++)
#pragma unroll
                for (int nt = 0; nt < 4; nt++) {
                    const int np = nt >> 1, bi = (nt & 1) * 2;
                    mma_bf16(acc[mt][nt], ax[mt], bh[np][bi], bh[np][bi + 1]);
                }

            // ---- term 2: Ah * Bl (Ah still resident) ----
#pragma unroll
            for (int mt = 0; mt < 4; mt++)
#pragma unroll
                for (int nt = 0; nt < 4; nt++) {
                    const int np = nt >> 1, bi = (nt & 1) * 2;
                    mma_bf16(acc[mt][nt], ax[mt], bl[np][bi], bl[np][bi + 1]);
                }

            // ---- term 3: Al * Bh (load Al over ax; Bh resident) ----
#pragma unroll
            for (int mt = 0; mt < 4; mt++) ldmx4(ax[mt], stb + 1 * GTILE_B + a_off[mt] + ko);
#pragma unroll
            for (int mt = 0; mt < 4; mt++)
#pragma unroll
                for (int nt = 0; nt < 4; nt++) {
                    const int np = nt >> 1, bi = (nt & 1) * 2;
                    mma_bf16(acc[mt][nt], ax[mt], bh[np][bi], bh[np][bi + 1]);
                }
        }

        __syncthreads();
        const int cn = c + 2;
        if (cn < NC)
            fill_stage(stb, Ah0 + cn * GKC, Al0 + cn * GKC,
                       Bh0 + cn * GKC, Bl0 + cn * GKC, K, tid);
    }

    const int rr = lane >> 2, cc = (lane & 3) * 2;

    if (!fused) {
        // plain fp32 epilogue
#pragma unroll
        for (int mt = 0; mt < 4; mt++) {
            const size_t mA = (size_t)(m0 + wm * 64 + mt * 16 + rr);
#pragma unroll
            for (int nt = 0; nt < 4; nt++) {
                const int n = n0 + wn * 32 + nt * 8 + cc;
                *(float2*)(C + mA * N + n) =
                    make_float2(acc[mt][nt][0], acc[mt][nt][1]);
                *(float2*)(C + (mA + 8) * N + n) =
                    make_float2(acc[mt][nt][2], acc[mt][nt][3]);
            }
        }
        return;
    }

    // fused QKV epilogue: segment by packed column
    if (n0 >= QCOLS + KCOLS) {
        // V segment: plain fp32 into Vb (stride KCOLS)
#pragma unroll
        for (int mt = 0; mt < 4; mt++) {
            const size_t mA = (size_t)(m0 + wm * 64 + mt * 16 + rr);
#pragma unroll
            for (int nt = 0; nt < 4; nt++) {
                const int n = (n0 - (QCOLS + KCOLS)) + wn * 32 + nt * 8 + cc;
                *(float2*)(Vb + mA * KCOLS + n) =
                    make_float2(acc[mt][nt][0], acc[mt][nt][1]);
                *(float2*)(Vb + (mA + 8) * KCOLS + n) =
                    make_float2(acc[mt][nt][2], acc[mt][nt][3]);
            }
        }
        return;
    }

    // Q or K segment: RoPE + bf16 split, write un-permuted layout
    __nv_bfloat16 *Xh, *Xl;
    int xs, segbase;
    if (n0 < QCOLS) { Xh = Qh; Xl = Ql; xs = QCOLS; segbase = 0; }
    else            { Xh = Kh; Xl = Kl; xs = KCOLS; segbase = QCOLS; }

#pragma unroll
    for (int mt = 0; mt < 4; mt++) {
        const int mA = m0 + wm * 64 + mt * 16 + rr;
#pragma unroll
        for (int nt = 0; nt < 4; nt++) {
            const int colp = (n0 - segbase) + wn * 32 + nt * 8 + cc; // even
            const int head = colp >> 8;
            const int i    = (colp & 255) >> 1;        // 0..127
            const int ca   = head * 256 + i;
            const int cb   = ca + 128;
#pragma unroll
            for (int rh = 0; rh < 2; rh++) {
                const int m   = mA + rh * 8;
                const int pos = m & (SEQ - 1);
                const float co = g_cos[pos * 128 + i];
                const float si = g_sin[pos * 128 + i];
                const float x1 = acc[mt][nt][rh * 2 + 0];
                const float x2 = acc[mt][nt][rh * 2 + 1];
                const float y1 = x1 * co - x2 * si;
                const float y2 = x2 * co + x1 * si;
                const __nv_bfloat16 h1 = __float2bfloat16(y1);
                const __nv_bfloat16 h2 = __float2bfloat16(y2);
                const size_t rb = (size_t)m * xs;
                Xh[rb + ca] = h1;
                Xh[rb + cb] = h2;
                Xl[rb + ca] = __float2bfloat16(y1 - __bfloat162float(h1));
                Xl[rb + cb] = __float2bfloat16(y2 - __bfloat162float(h2));
            }
        }
    }
}

// ---------------------------------------------------------------------------
// Tensor-core flash attention, bf16x3, no-max softmax (|logit| <= 50),
// FMA-pipe exp/rcp (zero MUFU in the hot path). Unchanged from passing R11.
// ---------------------------------------------------------------------------
#define DST 264   // Q/K smem row stride (bf16)
#define VST 72    // Vt smem row stride (bf16)
#define PST 72    // P smem row stride (bf16)
#define oQh 0
#define oQl 33792
#define oKh 67584
#define oKl 101376
#define oVh 135168
#define oVl 172032
#define oPh 208896
#define oPl 218112
#define oLrow 227328
#define ATTN_SMEM (227328 + 256)

__global__ void __launch_bounds__(256, 1)
attn_tc_kernel(const __nv_bfloat16* __restrict__ Qh, const __nv_bfloat16* __restrict__ Ql,
               const __nv_bfloat16* __restrict__ Kh, const __nv_bfloat16* __restrict__ Kl,
               const __nv_bfloat16* __restrict__ Vth, const __nv_bfloat16* __restrict__ Vtl,
               __nv_bfloat16* __restrict__ Ch, __nv_bfloat16* __restrict__ Cl)
{
    extern __shared__ char smraw[];
    const uint32_t sb = smem_u32(smraw);
    float* lrow = (float*)(smraw + oLrow);

    const int tid = threadIdx.x;
    const int wid = tid >> 5, lane = tid & 31;
    const int wq = wid & 3, wh = wid >> 2;
    const int b  = blockIdx.y >> 4;
    const int h  = blockIdx.y & 15;
    const int kvh = h >> 1;
    const int q0 = blockIdx.x * 64;

    const char* gQh = (const char*)(Qh + ((size_t)(b * SEQ + q0)) * QCOLS + h * HDIM);
    const char* gQl = (const char*)(Ql + ((size_t)(b * SEQ + q0)) * QCOLS + h * HDIM);
    const char* gKh = (const char*)(Kh + ((size_t)(b * SEQ)) * KCOLS + kvh * HDIM);
    const char* gKl = (const char*)(Kl + ((size_t)(b * SEQ)) * KCOLS + kvh * HDIM);
    const char* gVh = (const char*)(Vth + ((size_t)(b * KCOLS + kvh * HDIM)) * SEQ);
    const char* gVl = (const char*)(Vtl + ((size_t)(b * KCOLS + kvh * HDIM)) * SEQ);

    if (tid < 64) lrow[tid] = 0.f;

    int klo = q0 - WINDOW;       if (klo < 0) klo = 0;
    int khi = q0 + 64 + WINDOW;  if (khi > SEQ) khi = SEQ;
    const int kt0 = klo >> 6;
    const int ntiles = (khi >> 6) - kt0;

#pragma unroll
    for (int i = 0; i < 8; i++) {
        int id = tid + i * 256;
        int row = id >> 5, ch = id & 31;
        cp16(sb + oQh + row * (DST * 2) + ch * 16, gQh + (size_t)row * (QCOLS * 2) + ch * 16);
        cp16(sb + oQl + row * (DST * 2) + ch * 16, gQl + (size_t)row * (QCOLS * 2) + ch * 16);
    }
    {
        int kb = kt0 * 64;
#pragma unroll
        for (int i = 0; i < 8; i++) {
            int id = tid + i * 256;
            int row = id >> 5, ch = id & 31;
            cp16(sb + oKh + row * (DST * 2) + ch * 16, gKh + (size_t)(kb + row) * (KCOLS * 2) + ch * 16);
            cp16(sb + oKl + row * (DST * 2) + ch * 16, gKl + (size_t)(kb + row) * (KCOLS * 2) + ch * 16);
        }
        asm volatile("cp.async.commit_group;" ::: "memory");
#pragma unroll
        for (int i = 0; i < 8; i++) {
            int id = tid + i * 256;
            int row = id >> 3, ch = id & 7;
            cp16(sb + oVh + row * (VST * 2) + ch * 16, gVh + (size_t)row * (SEQ * 2) + kb * 2 + ch * 16);
            cp16(sb + oVl + row * (VST * 2) + ch * 16, gVl + (size_t)row * (SEQ * 2) + kb * 2 + ch * 16);
        }
        asm volatile("cp.async.commit_group;" ::: "memory");
    }
    asm volatile("cp.async.wait_group %0;" :: "n"(1) : "memory");
    __syncthreads();

    const uint32_t a_off = ((wq * 16 + (lane & 15)) * DST + (lane >> 4) * 8) * 2;
    uint32_t bs_off[2];
#pragma unroll
    for (int np = 0; np < 2; np++)
        bs_off[np] = ((wh * 32 + np * 16 + (lane & 7) + ((lane >> 4) & 1) * 8) * DST
                      + ((lane >> 3) & 1) * 8) * 2;
    const uint32_t ap_off = ((wq * 16 + (lane & 15)) * PST + (lane >> 4) * 8) * 2;
    uint32_t bv_off[8];
#pragma unroll
    for (int np = 0; np < 8; np++)
        bv_off[np] = ((wh * 128 + np * 16 + (lane & 7) + ((lane >> 4) & 1) * 8) * VST
                      + ((lane >> 3) & 1) * 8) * 2;

    float oacc[16][4];
#pragma unroll
    for (int nt = 0; nt < 16; nt++)
#pragma unroll
        for (int r = 0; r < 4; r++) oacc[nt][r] = 0.f;

    const int r0 = wq * 16 + (lane >> 2), r1 = r0 + 8;
    const int qg0 = q0 + r0, qg1 = q0 + r1;

    for (int t = 0; t < ntiles; t++) {
        const int kbase = (kt0 + t) * 64;

        float sacc[4][4];
#pragma unroll
        for (int nt = 0; nt < 4; nt++)
#pragma unroll
            for (int r = 0; r < 4; r++) sacc[nt][r] = 0.f;

#pragma unroll 4
        for (int ks = 0; ks < 16; ks++) {
            const uint32_t ko = ks * 32;
            uint32_t qhf[4], qlf[4], khf[2][4], klf[2][4];
            ldmx4(qhf, sb + oQh + a_off + ko);
            ldmx4(qlf, sb + oQl + a_off + ko);
#pragma unroll
            for (int np = 0; np < 2; np++) {
                ldmx4(khf[np], sb + oKh + bs_off[np] + ko);
                ldmx4(klf[np], sb + oKl + bs_off[np] + ko);
            }
#pragma unroll
            for (int nt = 0; nt < 4; nt++) {
                const int np = nt >> 1, bi = (nt & 1) * 2;
                mma_bf16(sacc[nt], qhf, khf[np][bi], khf[np][bi + 1]);
                mma_bf16(sacc[nt], qlf, khf[np][bi], khf[np][bi + 1]);
                mma_bf16(sacc[nt], qhf, klf[np][bi], klf[np][bi + 1]);
            }
        }

        float psum0 = 0.f, psum1 = 0.f;
#pragma unroll
        for (int nt = 0; nt < 4; nt++) {
            const int cl = wh * 32 + nt * 8 + (lane & 3) * 2;
            const int cg = kbase + cl;
            float p[4];
#pragma unroll
            for (int e = 0; e < 4; e++) {
                const int qg = (e < 2) ? qg0 : qg1;
                const int kg = cg + (e & 1);
                int dlt = qg - kg; if (dlt < 0) dlt = -dlt;
                if (dlt <= WINDOW) {
                    float E = fexp(sacc[nt][e] * 0.0025f);
                    float l = fmaf(-100.f, frcp(E + 1.f), 50.f);
                    p[e] = fexp(l);
                } else p[e] = 0.f;
            }
            psum0 += p[0] + p[1];
            psum1 += p[2] + p[3];
            __nv_bfloat16 h0 = __float2bfloat16(p[0]), h1 = __float2bfloat16(p[1]);
            __nv_bfloat16 h2 = __float2bfloat16(p[2]), h3 = __float2bfloat16(p[3]);
            *(__nv_bfloat162*)(smraw + oPh + (r0 * PST + cl) * 2) = __halves2bfloat162(h0, h1);
            *(__nv_bfloat162*)(smraw + oPh + (r1 * PST + cl) * 2) = __halves2bfloat162(h2, h3);
            *(__nv_bfloat162*)(smraw + oPl + (r0 * PST + cl) * 2) =
                __halves2bfloat162(__float2bfloat16(p[0] - __bfloat162float(h0)),
                                   __float2bfloat16(p[1] - __bfloat162float(h1)));
            *(__nv_bfloat162*)(smraw + oPl + (r1 * PST + cl) * 2) =
                __halves2bfloat162(__float2bfloat16(p[2] - __bfloat162float(h2)),
                                   __float2bfloat16(p[3] - __bfloat162float(h3)));
        }
        psum0 += __shfl_xor_sync(0xffffffffu, psum0, 1);
        psum0 += __shfl_xor_sync(0xffffffffu, psum0, 2);
        psum1 += __shfl_xor_sync(0xffffffffu, psum1, 1);
        psum1 += __shfl_xor_sync(0xffffffffu, psum1, 2);
        if ((lane & 3) == 0) {
            atomicAdd(&lrow[r0], psum0);
            atomicAdd(&lrow[r1], psum1);
        }

        asm volatile("cp.async.wait_group %0;" :: "n"(0) : "memory");
        __syncthreads();

        if (t + 1 < ntiles) {
            int kb = kbase + 64;
#pragma unroll
            for (int i = 0; i < 8; i++) {
                int id = tid + i * 256;
                int row = id >> 5, ch = id & 31;
                cp16(sb + oKh + row * (DST * 2) + ch * 16, gKh + (size_t)(kb + row) * (KCOLS * 2) + ch * 16);
                cp16(sb + oKl + row * (DST * 2) + ch * 16, gKl + (size_t)(kb + row) * (KCOLS * 2) + ch * 16);
            }
            asm volatile("cp.async.commit_group;" ::: "memory");
        }

#pragma unroll
        for (int kp = 0; kp < 4; kp++) {
            const uint32_t ko = kp * 32;
            uint32_t pah[4], pal[4];
            ldmx4(pah, sb + oPh + ap_off + ko);
            ldmx4(pal, sb + oPl + ap_off + ko);
#pragma unroll
            for (int np = 0; np < 8; np++) {
                uint32_t vbh[4], vbl[4];
                ldmx4(vbh, sb + oVh + bv_off[np] + ko);
                ldmx4(vbl, sb + oVl + bv_off[np] + ko);
#pragma unroll
                for (int i = 0; i < 2; i++) {
                    const int nt = np * 2 + i, bi = i * 2;
                    mma_bf16(oacc[nt], pah, vbh[bi], vbh[bi + 1]);
                    mma_bf16(oacc[nt], pal, vbh[bi], vbh[bi + 1]);
                    mma_bf16(oacc[nt], pah, vbl[bi], vbl[bi + 1]);
                }
            }
        }
        __syncthreads();

        if (t + 1 < ntiles) {
            int kb = kbase + 64;
#pragma unroll
            for (int i = 0; i < 8; i++) {
                int id = tid + i * 256;
                int row = id >> 3, ch = id & 7;
                cp16(sb + oVh + row * (VST * 2) + ch * 16, gVh + (size_t)row * (SEQ * 2) + kb * 2 + ch * 16);
                cp16(sb + oVl + row * (VST * 2) + ch * 16, gVl + (size_t)row * (SEQ * 2) + kb * 2 + ch * 16);
            }
            asm volatile("cp.async.commit_group;" ::: "memory");
            asm volatile("cp.async.wait_group %0;" :: "n"(1) : "memory");
        }
        __syncthreads();
    }

    const float inv0 = 1.0f / lrow[r0];
    const float inv1 = 1.0f / lrow[r1];
    const size_t row0 = (size_t)(b * SEQ + q0 + r0) * QCOLS;
    const size_t row1 = (size_t)(b * SEQ + q0 + r1) * QCOLS;
#pragma unroll
    for (int nt = 0; nt < 16; nt++) {
        const int col = h * HDIM + wh * 128 + nt * 8 + (lane & 3) * 2;
        float v0 = oacc[nt][0] * inv0, v1 = oacc[nt][1] * inv0;
        float v2 = oacc[nt][2] * inv1, v3 = oacc[nt][3] * inv1;
        __nv_bfloat16 h0 = __float2bfloat16(v0), h1 = __float2bfloat16(v1);
        __nv_bfloat16 h2 = __float2bfloat16(v2), h3 = __float2bfloat16(v3);
        *(__nv_bfloat162*)(Ch + row0 + col) = __halves2bfloat162(h0, h1);
        *(__nv_bfloat162*)(Ch + row1 + col) = __halves2bfloat162(h2, h3);
        *(__nv_bfloat162*)(Cl + row0 + col) =
            __halves2bfloat162(__float2bfloat16(v0 - __bfloat162float(h0)),
                               __float2bfloat16(v1 - __bfloat162float(h1)));
        *(__nv_bfloat162*)(Cl + row1 + col) =
            __halves2bfloat162(__float2bfloat16(v2 - __bfloat162float(h2)),
                               __float2bfloat16(v3 - __bfloat162float(h3)));
    }
}

// ---------------------------------------------------------------------------
// launch
// ---------------------------------------------------------------------------
extern "C" void kernel_launch(void* const* d_in, const int* in_sizes, int n_in,
                              void* d_out, int out_size)
{
    const float* hid = (const float*)d_in[0];
    const float* Wq  = (const float*)d_in[1];
    const float* Wk  = (const float*)d_in[2];
    const float* Wv  = (const float*)d_in[3];
    const float* Wo  = (const float*)d_in[4];
    float* out = (float*)d_out;

    float *Vb;
    cudaGetSymbolAddress((void**)&Vb, g_V);

    __nv_bfloat16 *Hh, *Hl, *WpH, *WpL, *WotH, *WotL;
    __nv_bfloat16 *Ch, *Cl, *Qh, *Ql, *Kh, *Kl, *VtH, *VtL;
    cudaGetSymbolAddress((void**)&Hh,   g_Hh);
    cudaGetSymbolAddress((void**)&Hl,   g_Hl);
    cudaGetSymbolAddress((void**)&WpH,  g_WpH);
    cudaGetSymbolAddress((void**)&WpL,  g_WpL);
    cudaGetSymbolAddress((void**)&WotH, g_WotH);
    cudaGetSymbolAddress((void**)&WotL, g_WotL);
    cudaGetSymbolAddress((void**)&Ch,   g_Ch);
    cudaGetSymbolAddress((void**)&Cl,   g_Cl);
    cudaGetSymbolAddress((void**)&Qh,   g_Qh);
    cudaGetSymbolAddress((void**)&Ql,   g_Ql);
    cudaGetSymbolAddress((void**)&Kh,   g_Kh);
    cudaGetSymbolAddress((void**)&Kl,   g_Kl);
    cudaGetSymbolAddress((void**)&VtH,  g_VtH);
    cudaGetSymbolAddress((void**)&VtL,  g_VtL);

    cudaFuncSetAttribute(gemm_mma_kernel, cudaFuncAttributeMaxDynamicSharedMemorySize,
                         GEMM_SMEM);
    cudaFuncSetAttribute(attn_tc_kernel, cudaFuncAttributeMaxDynamicSharedMemorySize,
                         ATTN_SMEM);

    rope_tables_kernel<<<(SEQ * 128 + 255) / 256, 256>>>();

    // splits / transposes of inputs (Q/K permuted for RoPE-fused epilogue)
    split_kernel<<<(MROWS * EMBED / 4 + 255) / 256, 256>>>(hid, Hh, Hl, MROWS * EMBED / 4);
    tsplit_kernel<<<dim3(QCOLS / 32, EMBED / 32), dim3(32, 8)>>>(Wq, WpH, WpL, EMBED, QCOLS, 1, 0);
    tsplit_kernel<<<dim3(KCOLS / 32, EMBED / 32), dim3(32, 8)>>>(Wk, WpH, WpL, EMBED, KCOLS, 1, QCOLS);
    tsplit_kernel<<<dim3(KCOLS / 32, EMBED / 32), dim3(32, 8)>>>(Wv, WpH, WpL, EMBED, KCOLS, 0, QCOLS + KCOLS);
    tsplit_kernel<<<dim3(EMBED / 32, QCOLS / 32), dim3(32, 8)>>>(Wo, WotH, WotL, QCOLS, EMBED, 0, 0);

    // fused QKV projection: RoPE+split epilogue for Q/K, fp32 for V
    gemm_mma_kernel<<<dim3(NPACK / 128, MROWS / 128), 256, GEMM_SMEM>>>(
        Hh, Hl, WpH, WpL, nullptr, MROWS, NPACK, EMBED,
        1, Qh, Ql, Kh, Kl, Vb);

    // V transpose+split
    vtsplit_kernel<<<dim3(SEQ / 32, KCOLS / 32, BATCH), dim3(32, 8)>>>(Vb, VtH, VtL);

    // tensor-core attention -> Ch/Cl bf16 splits
    attn_tc_kernel<<<dim3(SEQ / 64, BATCH * NH), 256, ATTN_SMEM>>>(
        Qh, Ql, Kh, Kl, VtH, VtL, Ch, Cl);

    // output projection straight into d_out
    gemm_mma_kernel<<<dim3(EMBED / 128, MROWS / 128), 256, GEMM_SMEM>>>(
        Ch, Cl, WotH, WotL, out, MROWS, EMBED, QCOLS,
        0, nullptr, nullptr, nullptr, nullptr, nullptr);
}

// round 13
// speedup vs baseline: 1.0112x; 1.0112x over previous
#include <cuda_runtime.h>
#include <cuda_bf16.h>
#include <math.h>
#include <stdint.h>

// ---------------------------------------------------------------------------
// Problem constants
// ---------------------------------------------------------------------------
#define BATCH   2
#define SEQ     2048
#define EMBED   3584
#define NH      16
#define NKV     8
#define HDIM    256
#define MROWS   (BATCH*SEQ)          // 4096
#define QCOLS   (NH*HDIM)            // 4096
#define KCOLS   (NKV*HDIM)           // 2048
#define NPACK   (QCOLS + 2*KCOLS)    // 8192 packed QKV columns
#define WINDOW  1024

// ---------------------------------------------------------------------------
// Static device scratch (no cudaMalloc allowed)
// ---------------------------------------------------------------------------
__device__ float g_V  [(size_t)MROWS*KCOLS];
__device__ float g_cos[SEQ*(HDIM/2)];
__device__ float g_sin[SEQ*(HDIM/2)];

// bf16 hi/lo splits
__device__ __nv_bfloat16 g_Hh [(size_t)MROWS*EMBED];
__device__ __nv_bfloat16 g_Hl [(size_t)MROWS*EMBED];
__device__ __nv_bfloat16 g_WpH[(size_t)NPACK*EMBED];   // packed Wq|Wk|Wv, transposed+split
__device__ __nv_bfloat16 g_WpL[(size_t)NPACK*EMBED];
__device__ __nv_bfloat16 g_WotH[(size_t)EMBED*QCOLS];
__device__ __nv_bfloat16 g_WotL[(size_t)EMBED*QCOLS];
__device__ __nv_bfloat16 g_Ch  [(size_t)MROWS*QCOLS];
__device__ __nv_bfloat16 g_Cl  [(size_t)MROWS*QCOLS];

// attention operands (bf16 splits)
__device__ __nv_bfloat16 g_Qh [(size_t)MROWS*QCOLS];
__device__ __nv_bfloat16 g_Ql [(size_t)MROWS*QCOLS];
__device__ __nv_bfloat16 g_Kh [(size_t)MROWS*KCOLS];
__device__ __nv_bfloat16 g_Kl [(size_t)MROWS*KCOLS];
__device__ __nv_bfloat16 g_VtH[(size_t)MROWS*KCOLS];   // per-batch transposed [KCOLS][SEQ]
__device__ __nv_bfloat16 g_VtL[(size_t)MROWS*KCOLS];

// ---------------------------------------------------------------------------
// PTX helpers (sm_100-safe: no tcgen05, no clusters)
// ---------------------------------------------------------------------------
__device__ __forceinline__ uint32_t smem_u32(const void* p) {
    uint32_t a;
    asm("{ .reg .u64 t; cvta.to.shared.u64 t, %1; cvt.u32.u64 %0, t; }" : "=r"(a) : "l"(p));
    return a;
}
__device__ __forceinline__ void cp16(uint32_t dst, const void* src) {
    asm volatile("cp.async.cg.shared.global [%0], [%1], 16;" :: "r"(dst), "l"(src) : "memory");
}
__device__ __forceinline__ void ldmx4(uint32_t* r, uint32_t addr) {
    asm volatile("ldmatrix.sync.aligned.m8n8.x4.shared.b16 {%0,%1,%2,%3}, [%4];"
                 : "=r"(r[0]), "=r"(r[1]), "=r"(r[2]), "=r"(r[3]) : "r"(addr));
}
__device__ __forceinline__ void mma_bf16(float* c, const uint32_t* a,
                                         uint32_t b0, uint32_t b1) {
    asm volatile(
        "mma.sync.aligned.m16n8k16.row.col.f32.bf16.bf16.f32 "
        "{%0,%1,%2,%3}, {%4,%5,%6,%7}, {%8,%9}, {%0,%1,%2,%3};"
        : "+f"(c[0]), "+f"(c[1]), "+f"(c[2]), "+f"(c[3])
        : "r"(a[0]), "r"(a[1]), "r"(a[2]), "r"(a[3]), "r"(b0), "r"(b1));
}

// FMA-pipe exp (no MUFU): e^x for |x| <= ~85, rel err ~1.5e-7
__device__ __forceinline__ float fexp(float x) {
    float y  = x * 1.4426950408889634f;          // log2(e)
    float fm = y + 12582912.0f;                  // round-to-nearest via magic
    float nf = fm - 12582912.0f;
    float f  = y - nf;                           // [-0.5, 0.5]
    int   sc = ((__float_as_int(fm) - 0x4B400000) + 127) << 23;
    float t  = f * 0.6931471805599453f;
    float p  = 1.0f + t*(1.0f + t*(0.5f + t*(0.16666667f +
               t*(0.041666667f + t*(0.008333334f + t*0.0013888889f)))));
    return p * __int_as_float(sc);
}
// FMA-pipe reciprocal (bit-hack + 3 Newton)
__device__ __forceinline__ float frcp(float d) {
    float r = __int_as_float(0x7EF311C3 - __float_as_int(d));
    r = r * (2.0f - d * r);
    r = r * (2.0f - d * r);
    r = r * (2.0f - d * r);
    return r;
}

// ---------------------------------------------------------------------------
// fp32 -> bf16 hi/lo split (vectorized)
// ---------------------------------------------------------------------------
__global__ void split_kernel(const float* __restrict__ in,
                             __nv_bfloat16* __restrict__ hi,
                             __nv_bfloat16* __restrict__ lo, int n4)
{
    int i = blockIdx.x * 256 + threadIdx.x;
    if (i >= n4) return;
    float4 v = ((const float4*)in)[i];
    __nv_bfloat16 h0 = __float2bfloat16(v.x);
    __nv_bfloat16 h1 = __float2bfloat16(v.y);
    __nv_bfloat16 h2 = __float2bfloat16(v.z);
    __nv_bfloat16 h3 = __float2bfloat16(v.w);
    __nv_bfloat16 l0 = __float2bfloat16(v.x - __bfloat162float(h0));
    __nv_bfloat16 l1 = __float2bfloat16(v.y - __bfloat162float(h1));
    __nv_bfloat16 l2 = __float2bfloat16(v.z - __bfloat162float(h2));
    __nv_bfloat16 l3 = __float2bfloat16(v.w - __bfloat162float(h3));
    ((__nv_bfloat162*)hi)[2*i]   = __halves2bfloat162(h0, h1);
    ((__nv_bfloat162*)hi)[2*i+1] = __halves2bfloat162(h2, h3);
    ((__nv_bfloat162*)lo)[2*i]   = __halves2bfloat162(l0, l1);
    ((__nv_bfloat162*)lo)[2*i+1] = __halves2bfloat162(l2, l3);
}

// ---------------------------------------------------------------------------
// Transpose + split: W [K,N] fp32 -> Th/Tl rows [rowoff + perm(n)][K] bf16.
// perm=1 interleaves RoPE pairs: col i<128 -> 2i, col i>=128 -> 2(i-128)+1
// ---------------------------------------------------------------------------
__global__ void tsplit_kernel(const float* __restrict__ W,
                              __nv_bfloat16* __restrict__ Th,
                              __nv_bfloat16* __restrict__ Tl, int K, int N,
                              int perm, int rowoff)
{
    __shared__ float t[32][33];
    int n0 = blockIdx.x * 32, k0 = blockIdx.y * 32;
    int tx = threadIdx.x, ty = threadIdx.y;
#pragma unroll
    for (int i = 0; i < 32; i += 8)
        t[ty + i][tx] = W[(size_t)(k0 + ty + i) * N + n0 + tx];
    __syncthreads();
#pragma unroll
    for (int i = 0; i < 32; i += 8) {
        float v = t[tx][ty + i];
        __nv_bfloat16 h = __float2bfloat16(v);
        __nv_bfloat16 l = __float2bfloat16(v - __bfloat162float(h));
        int n = n0 + ty + i;
        int nb = n & 255;
        int np = perm ? ((n & ~255) + ((nb < 128) ? (nb << 1) : (((nb - 128) << 1) | 1)))
                      : n;
        size_t o = (size_t)(rowoff + np) * K + k0 + tx;
        Th[o] = h;
        Tl[o] = l;
    }
}

// ---------------------------------------------------------------------------
// V transpose+split per batch: g_V [b*SEQ+s][KCOLS] -> Vt [b][KCOLS][SEQ]
// ---------------------------------------------------------------------------
__global__ void vtsplit_kernel(const float* __restrict__ V,
                               __nv_bfloat16* __restrict__ Th,
                               __nv_bfloat16* __restrict__ Tl)
{
    __shared__ float t[32][33];
    int s0 = blockIdx.x * 32, c0 = blockIdx.y * 32, b = blockIdx.z;
    int tx = threadIdx.x, ty = threadIdx.y;
#pragma unroll
    for (int i = 0; i < 32; i += 8)
        t[ty + i][tx] = V[((size_t)b * SEQ + s0 + ty + i) * KCOLS + c0 + tx];
    __syncthreads();
#pragma unroll
    for (int i = 0; i < 32; i += 8) {
        float v = t[tx][ty + i];
        __nv_bfloat16 h = __float2bfloat16(v);
        __nv_bfloat16 l = __float2bfloat16(v - __bfloat162float(h));
        size_t o = ((size_t)b * KCOLS + c0 + ty + i) * SEQ + s0 + tx;
        Th[o] = h;
        Tl[o] = l;
    }
}

// ---------------------------------------------------------------------------
// RoPE tables (double precision)
// ---------------------------------------------------------------------------
__global__ void rope_tables_kernel()
{
    int idx = blockIdx.x * 256 + threadIdx.x;
    if (idx >= SEQ * (HDIM / 2)) return;
    int i = idx & 127;
    int pos = idx >> 7;
    double invf = pow(10000.0, -(double)(2 * i) / (double)HDIM);
    double ang = (double)pos * invf;
    g_cos[idx] = (float)cos(ang);
    g_sin[idx] = (float)sin(ang);
}

// ---------------------------------------------------------------------------
// mma.sync bf16x3 GEMM: 2-stage pipeline, 2 CTAs/SM, R11 term ordering,
// L2-friendly supertile grid rasterization (W=16 n-tiles per column).
// mode 0: C[M,N] fp32 plain.
// mode 1: fused QKV: RoPE epilogue -> Qh/Ql/Kh/Kl; V segment -> Vb fp32.
// ---------------------------------------------------------------------------
#define GKC       32
#define GSTRIDE   40
#define GTILE_B   (128*GSTRIDE*2)    // 10240 B per tile
#define GSTAGE_B  (4*GTILE_B)        // Ah, Al, Bh, Bl = 40960 B
#define GEMM_SMEM (2*GSTAGE_B)       // 81920 B -> 2 CTAs/SM
#define GSW       16                 // supertile width (n-tiles)

__device__ __forceinline__ void fill_stage(uint32_t stb,
                                           const __nv_bfloat16* Ah0,
                                           const __nv_bfloat16* Al0,
                                           const __nv_bfloat16* Bh0,
                                           const __nv_bfloat16* Bl0,
                                           int K, int tid)
{
    const __nv_bfloat16* srcs[4] = {Ah0, Al0, Bh0, Bl0};
#pragma unroll
    for (int t = 0; t < 4; t++) {
        uint32_t tb = stb + t * GTILE_B;
        const char* s = (const char*)srcs[t];
#pragma unroll
        for (int i = 0; i < 2; i++) {
            int id = tid + i * 256;
            int row = id >> 2, ch = id & 3;
            cp16(tb + row * (GSTRIDE * 2) + ch * 16,
                 s + (size_t)row * K * 2 + ch * 16);
        }
    }
    asm volatile("cp.async.commit_group;" ::: "memory");
}

__global__ void __launch_bounds__(256, 2)
gemm_mma_kernel(const __nv_bfloat16* __restrict__ Ah,
                const __nv_bfloat16* __restrict__ Al,
                const __nv_bfloat16* __restrict__ Bh,
                const __nv_bfloat16* __restrict__ Bl,
                float* __restrict__ C, int M, int N, int K,
                int fused,
                __nv_bfloat16* __restrict__ Qh, __nv_bfloat16* __restrict__ Ql,
                __nv_bfloat16* __restrict__ Kh, __nv_bfloat16* __restrict__ Kl,
                float* __restrict__ Vb)
{
    extern __shared__ char gsm[];
    const uint32_t sbase = smem_u32(gsm);
    const int tid = threadIdx.x;
    const int wid = tid >> 5, lane = tid & 31;
    const int wm = wid & 1, wn = wid >> 1;

    // ---- supertile rasterization: columns of GSW n-tiles x all m-tiles ----
    const int Mt = M >> 7, Ntl = N >> 7;
    int mtile, ntile;
    {
        const int bid = blockIdx.x;
        const int per = GSW * Mt;
        const int fullcols = Ntl / GSW;
        if (bid < fullcols * per) {
            const int col = bid / per;
            const int r = bid % per;
            mtile = r / GSW;
            ntile = col * GSW + r % GSW;
        } else {
            const int r = bid - fullcols * per;
            const int wdt = Ntl - fullcols * GSW;
            mtile = r / wdt;
            ntile = fullcols * GSW + r % wdt;
        }
    }
    const int m0 = mtile * 128, n0 = ntile * 128;

    uint32_t a_off[4], b_off[2];
#pragma unroll
    for (int mt = 0; mt < 4; mt++)
        a_off[mt] = ((wm * 64 + mt * 16 + (lane & 15)) * GSTRIDE
                     + (lane >> 4) * 8) * 2;
#pragma unroll
    for (int np = 0; np < 2; np++)
        b_off[np] = ((wn * 32 + np * 16 + (lane & 7) + ((lane >> 4) & 1) * 8) * GSTRIDE
                     + ((lane >> 3) & 1) * 8) * 2;

    const __nv_bfloat16* Ah0 = Ah + (size_t)m0 * K;
    const __nv_bfloat16* Al0 = Al + (size_t)m0 * K;
    const __nv_bfloat16* Bh0 = Bh + (size_t)n0 * K;
    const __nv_bfloat16* Bl0 = Bl + (size_t)n0 * K;

    float acc[4][4][4];
#pragma unroll
    for (int mt = 0; mt < 4; mt++)
#pragma unroll
        for (int nt = 0; nt < 4; nt++)
#pragma unroll
            for (int r = 0; r < 4; r++) acc[mt][nt][r] = 0.f;

    const int NC = K / GKC;

    // prologue: 2 stages in flight
#pragma unroll
    for (int c = 0; c < 2; c++)
        fill_stage(sbase + c * GSTAGE_B, Ah0 + c * GKC, Al0 + c * GKC,
                   Bh0 + c * GKC, Bl0 + c * GKC, K, tid);

    for (int c = 0; c < NC; c++) {
        const uint32_t stb = sbase + (c & 1) * GSTAGE_B;
        asm volatile("cp.async.wait_group %0;" :: "n"(1) : "memory");
        __syncthreads();

#pragma unroll
        for (int ks = 0; ks < 2; ks++) {
            const uint32_t ko = ks * 32;
            uint32_t ax[4][4], bx[2][4];

            // ---- term 1: Ah * Bh ----
#pragma unroll
            for (int mt = 0; mt < 4; mt++) ldmx4(ax[mt], stb + 0 * GTILE_B + a_off[mt] + ko);
#pragma unroll
            for (int np = 0; np < 2; np++) ldmx4(bx[np], stb + 2 * GTILE_B + b_off[np] + ko);
#pragma unroll
            for (int mt = 0; mt < 4; mt++)
#pragma unroll
                for (int nt = 0; nt < 4; nt++) {
                    const int np = nt >> 1, bi = (nt & 1) * 2;
                    mma_bf16(acc[mt][nt], ax[mt], bx[np][bi], bx[np][bi + 1]);
                }

            // ---- term 2: Al * Bh (reuse Bh frags) ----
#pragma unroll
            for (int mt = 0; mt < 4; mt++) ldmx4(ax[mt], stb + 1 * GTILE_B + a_off[mt] + ko);
#pragma unroll
            for (int mt = 0; mt < 4; mt++)
#pragma unroll
                for (int nt = 0; nt < 4; nt++) {
                    const int np = nt >> 1, bi = (nt & 1) * 2;
                    mma_bf16(acc[mt][nt], ax[mt], bx[np][bi], bx[np][bi + 1]);
                }

            // ---- term 3: Ah * Bl (reload Ah, load Bl) ----
#pragma unroll
            for (int mt = 0; mt < 4; mt++) ldmx4(ax[mt], stb + 0 * GTILE_B + a_off[mt] + ko);
#pragma unroll
            for (int np = 0; np < 2; np++) ldmx4(bx[np], stb + 3 * GTILE_B + b_off[np] + ko);
#pragma unroll
            for (int mt = 0; mt < 4; mt++)
#pragma unroll
                for (int nt = 0; nt < 4; nt++) {
                    const int np = nt >> 1, bi = (nt & 1) * 2;
                    mma_bf16(acc[mt][nt], ax[mt], bx[np][bi], bx[np][bi + 1]);
                }
        }

        __syncthreads();
        const int cn = c + 2;
        if (cn < NC)
            fill_stage(stb, Ah0 + cn * GKC, Al0 + cn * GKC,
                       Bh0 + cn * GKC, Bl0 + cn * GKC, K, tid);
    }

    const int rr = lane >> 2, cc = (lane & 3) * 2;

    if (!fused) {
        // plain fp32 epilogue
#pragma unroll
        for (int mt = 0; mt < 4; mt++) {
            const size_t mA = (size_t)(m0 + wm * 64 + mt * 16 + rr);
#pragma unroll
            for (int nt = 0; nt < 4; nt++) {
                const int n = n0 + wn * 32 + nt * 8 + cc;
                *(float2*)(C + mA * N + n) =
                    make_float2(acc[mt][nt][0], acc[mt][nt][1]);
                *(float2*)(C + (mA + 8) * N + n) =
                    make_float2(acc[mt][nt][2], acc[mt][nt][3]);
            }
        }
        return;
    }

    // fused QKV epilogue: segment by packed column
    if (n0 >= QCOLS + KCOLS) {
        // V segment: plain fp32 into Vb (stride KCOLS)
#pragma unroll
        for (int mt = 0; mt < 4; mt++) {
            const size_t mA = (size_t)(m0 + wm * 64 + mt * 16 + rr);
#pragma unroll
            for (int nt = 0; nt < 4; nt++) {
                const int n = (n0 - (QCOLS + KCOLS)) + wn * 32 + nt * 8 + cc;
                *(float2*)(Vb + mA * KCOLS + n) =
                    make_float2(acc[mt][nt][0], acc[mt][nt][1]);
                *(float2*)(Vb + (mA + 8) * KCOLS + n) =
                    make_float2(acc[mt][nt][2], acc[mt][nt][3]);
            }
        }
        return;
    }

    // Q or K segment: RoPE + bf16 split, write un-permuted layout
    __nv_bfloat16 *Xh, *Xl;
    int xs, segbase;
    if (n0 < QCOLS) { Xh = Qh; Xl = Ql; xs = QCOLS; segbase = 0; }
    else            { Xh = Kh; Xl = Kl; xs = KCOLS; segbase = QCOLS; }

#pragma unroll
    for (int mt = 0; mt < 4; mt++) {
        const int mA = m0 + wm * 64 + mt * 16 + rr;
#pragma unroll
        for (int nt = 0; nt < 4; nt++) {
            const int colp = (n0 - segbase) + wn * 32 + nt * 8 + cc; // even
            const int head = colp >> 8;
            const int i    = (colp & 255) >> 1;        // 0..127
            const int ca   = head * 256 + i;
            const int cb   = ca + 128;
#pragma unroll
            for (int rh = 0; rh < 2; rh++) {
                const int m   = mA + rh * 8;
                const int pos = m & (SEQ - 1);
                const float co = g_cos[pos * 128 + i];
                const float si = g_sin[pos * 128 + i];
                const float x1 = acc[mt][nt][rh * 2 + 0];
                const float x2 = acc[mt][nt][rh * 2 + 1];
                const float y1 = x1 * co - x2 * si;
                const float y2 = x2 * co + x1 * si;
                const __nv_bfloat16 h1 = __float2bfloat16(y1);
                const __nv_bfloat16 h2 = __float2bfloat16(y2);
                const size_t rb = (size_t)m * xs;
                Xh[rb + ca] = h1;
                Xh[rb + cb] = h2;
                Xl[rb + ca] = __float2bfloat16(y1 - __bfloat162float(h1));
                Xl[rb + cb] = __float2bfloat16(y2 - __bfloat162float(h2));
            }
        }
    }
}

// ---------------------------------------------------------------------------
// Tensor-core flash attention, bf16x3, no-max softmax (|logit| <= 50),
// FMA-pipe exp/rcp (zero MUFU in the hot path). Unchanged from passing R11.
// ---------------------------------------------------------------------------
#define DST 264   // Q/K smem row stride (bf16)
#define VST 72    // Vt smem row stride (bf16)
#define PST 72    // P smem row stride (bf16)
#define oQh 0
#define oQl 33792
#define oKh 67584
#define oKl 101376
#define oVh 135168
#define oVl 172032
#define oPh 208896
#define oPl 218112
#define oLrow 227328
#define ATTN_SMEM (227328 + 256)

__global__ void __launch_bounds__(256, 1)
attn_tc_kernel(const __nv_bfloat16* __restrict__ Qh, const __nv_bfloat16* __restrict__ Ql,
               const __nv_bfloat16* __restrict__ Kh, const __nv_bfloat16* __restrict__ Kl,
               const __nv_bfloat16* __restrict__ Vth, const __nv_bfloat16* __restrict__ Vtl,
               __nv_bfloat16* __restrict__ Ch, __nv_bfloat16* __restrict__ Cl)
{
    extern __shared__ char smraw[];
    const uint32_t sb = smem_u32(smraw);
    float* lrow = (float*)(smraw + oLrow);

    const int tid = threadIdx.x;
    const int wid = tid >> 5, lane = tid & 31;
    const int wq = wid & 3, wh = wid >> 2;
    const int b  = blockIdx.y >> 4;
    const int h  = blockIdx.y & 15;
    const int kvh = h >> 1;
    const int q0 = blockIdx.x * 64;

    const char* gQh = (const char*)(Qh + ((size_t)(b * SEQ + q0)) * QCOLS + h * HDIM);
    const char* gQl = (const char*)(Ql + ((size_t)(b * SEQ + q0)) * QCOLS + h * HDIM);
    const char* gKh = (const char*)(Kh + ((size_t)(b * SEQ)) * KCOLS + kvh * HDIM);
    const char* gKl = (const char*)(Kl + ((size_t)(b * SEQ)) * KCOLS + kvh * HDIM);
    const char* gVh = (const char*)(Vth + ((size_t)(b * KCOLS + kvh * HDIM)) * SEQ);
    const char* gVl = (const char*)(Vtl + ((size_t)(b * KCOLS + kvh * HDIM)) * SEQ);

    if (tid < 64) lrow[tid] = 0.f;

    int klo = q0 - WINDOW;       if (klo < 0) klo = 0;
    int khi = q0 + 64 + WINDOW;  if (khi > SEQ) khi = SEQ;
    const int kt0 = klo >> 6;
    const int ntiles = (khi >> 6) - kt0;

#pragma unroll
    for (int i = 0; i < 8; i++) {
        int id = tid + i * 256;
        int row = id >> 5, ch = id & 31;
        cp16(sb + oQh + row * (DST * 2) + ch * 16, gQh + (size_t)row * (QCOLS * 2) + ch * 16);
        cp16(sb + oQl + row * (DST * 2) + ch * 16, gQl + (size_t)row * (QCOLS * 2) + ch * 16);
    }
    {
        int kb = kt0 * 64;
#pragma unroll
        for (int i = 0; i < 8; i++) {
            int id = tid + i * 256;
            int row = id >> 5, ch = id & 31;
            cp16(sb + oKh + row * (DST * 2) + ch * 16, gKh + (size_t)(kb + row) * (KCOLS * 2) + ch * 16);
            cp16(sb + oKl + row * (DST * 2) + ch * 16, gKl + (size_t)(kb + row) * (KCOLS * 2) + ch * 16);
        }
        asm volatile("cp.async.commit_group;" ::: "memory");
#pragma unroll
        for (int i = 0; i < 8; i++) {
            int id = tid + i * 256;
            int row = id >> 3, ch = id & 7;
            cp16(sb + oVh + row * (VST * 2) + ch * 16, gVh + (size_t)row * (SEQ * 2) + kb * 2 + ch * 16);
            cp16(sb + oVl + row * (VST * 2) + ch * 16, gVl + (size_t)row * (SEQ * 2) + kb * 2 + ch * 16);
        }
        asm volatile("cp.async.commit_group;" ::: "memory");
    }
    asm volatile("cp.async.wait_group %0;" :: "n"(1) : "memory");
    __syncthreads();

    const uint32_t a_off = ((wq * 16 + (lane & 15)) * DST + (lane >> 4) * 8) * 2;
    uint32_t bs_off[2];
#pragma unroll
    for (int np = 0; np < 2; np++)
        bs_off[np] = ((wh * 32 + np * 16 + (lane & 7) + ((lane >> 4) & 1) * 8) * DST
                      + ((lane >> 3) & 1) * 8) * 2;
    const uint32_t ap_off = ((wq * 16 + (lane & 15)) * PST + (lane >> 4) * 8) * 2;
    uint32_t bv_off[8];
#pragma unroll
    for (int np = 0; np < 8; np++)
        bv_off[np] = ((wh * 128 + np * 16 + (lane & 7) + ((lane >> 4) & 1) * 8) * VST
                      + ((lane >> 3) & 1) * 8) * 2;

    float oacc[16][4];
#pragma unroll
    for (int nt = 0; nt < 16; nt++)
#pragma unroll
        for (int r = 0; r < 4; r++) oacc[nt][r] = 0.f;

    const int r0 = wq * 16 + (lane >> 2), r1 = r0 + 8;
    const int qg0 = q0 + r0, qg1 = q0 + r1;

    for (int t = 0; t < ntiles; t++) {
        const int kbase = (kt0 + t) * 64;

        float sacc[4][4];
#pragma unroll
        for (int nt = 0; nt < 4; nt++)
#pragma unroll
            for (int r = 0; r < 4; r++) sacc[nt][r] = 0.f;

#pragma unroll 4
        for (int ks = 0; ks < 16; ks++) {
            const uint32_t ko = ks * 32;
            uint32_t qhf[4], qlf[4], khf[2][4], klf[2][4];
            ldmx4(qhf, sb + oQh + a_off + ko);
            ldmx4(qlf, sb + oQl + a_off + ko);
#pragma unroll
            for (int np = 0; np < 2; np++) {
                ldmx4(khf[np], sb + oKh + bs_off[np] + ko);
                ldmx4(klf[np], sb + oKl + bs_off[np] + ko);
            }
#pragma unroll
            for (int nt = 0; nt < 4; nt++) {
                const int np = nt >> 1, bi = (nt & 1) * 2;
                mma_bf16(sacc[nt], qhf, khf[np][bi], khf[np][bi + 1]);
                mma_bf16(sacc[nt], qlf, khf[np][bi], khf[np][bi + 1]);
                mma_bf16(sacc[nt], qhf, klf[np][bi], klf[np][bi + 1]);
            }
        }

        float psum0 = 0.f, psum1 = 0.f;
#pragma unroll
        for (int nt = 0; nt < 4; nt++) {
            const int cl = wh * 32 + nt * 8 + (lane & 3) * 2;
            const int cg = kbase + cl;
            float p[4];
#pragma unroll
            for (int e = 0; e < 4; e++) {
                const int qg = (e < 2) ? qg0 : qg1;
                const int kg = cg + (e & 1);
                int dlt = qg - kg; if (dlt < 0) dlt = -dlt;
                if (dlt <= WINDOW) {
                    float E = fexp(sacc[nt][e] * 0.0025f);
                    float l = fmaf(-100.f, frcp(E + 1.f), 50.f);
                    p[e] = fexp(l);
                } else p[e] = 0.f;
            }
            psum0 += p[0] + p[1];
            psum1 += p[2] + p[3];
            __nv_bfloat16 h0 = __float2bfloat16(p[0]), h1 = __float2bfloat16(p[1]);
            __nv_bfloat16 h2 = __float2bfloat16(p[2]), h3 = __float2bfloat16(p[3]);
            *(__nv_bfloat162*)(smraw + oPh + (r0 * PST + cl) * 2) = __halves2bfloat162(h0, h1);
            *(__nv_bfloat162*)(smraw + oPh + (r1 * PST + cl) * 2) = __halves2bfloat162(h2, h3);
            *(__nv_bfloat162*)(smraw + oPl + (r0 * PST + cl) * 2) =
                __halves2bfloat162(__float2bfloat16(p[0] - __bfloat162float(h0)),
                                   __float2bfloat16(p[1] - __bfloat162float(h1)));
            *(__nv_bfloat162*)(smraw + oPl + (r1 * PST + cl) * 2) =
                __halves2bfloat162(__float2bfloat16(p[2] - __bfloat162float(h2)),
                                   __float2bfloat16(p[3] - __bfloat162float(h3)));
        }
        psum0 += __shfl_xor_sync(0xffffffffu, psum0, 1);
        psum0 += __shfl_xor_sync(0xffffffffu, psum0, 2);
        psum1 += __shfl_xor_sync(0xffffffffu, psum1, 1);
        psum1 += __shfl_xor_sync(0xffffffffu, psum1, 2);
        if ((lane & 3) == 0) {
            atomicAdd(&lrow[r0], psum0);
            atomicAdd(&lrow[r1], psum1);
        }

        asm volatile("cp.async.wait_group %0;" :: "n"(0) : "memory");
        __syncthreads();

        if (t + 1 < ntiles) {
            int kb = kbase + 64;
#pragma unroll
            for (int i = 0; i < 8; i++) {
                int id = tid + i * 256;
                int row = id >> 5, ch = id & 31;
                cp16(sb + oKh + row * (DST * 2) + ch * 16, gKh + (size_t)(kb + row) * (KCOLS * 2) + ch * 16);
                cp16(sb + oKl + row * (DST * 2) + ch * 16, gKl + (size_t)(kb + row) * (KCOLS * 2) + ch * 16);
            }
            asm volatile("cp.async.commit_group;" ::: "memory");
        }

#pragma unroll
        for (int kp = 0; kp < 4; kp++) {
            const uint32_t ko = kp * 32;
            uint32_t pah[4], pal[4];
            ldmx4(pah, sb + oPh + ap_off + ko);
            ldmx4(pal, sb + oPl + ap_off + ko);
#pragma unroll
            for (int np = 0; np < 8; np++) {
                uint32_t vbh[4], vbl[4];
                ldmx4(vbh, sb + oVh + bv_off[np] + ko);
                ldmx4(vbl, sb + oVl + bv_off[np] + ko);
#pragma unroll
                for (int i = 0; i < 2; i++) {
                    const int nt = np * 2 + i, bi = i * 2;
                    mma_bf16(oacc[nt], pah, vbh[bi], vbh[bi + 1]);
                    mma_bf16(oacc[nt], pal, vbh[bi], vbh[bi + 1]);
                    mma_bf16(oacc[nt], pah, vbl[bi], vbl[bi + 1]);
                }
            }
        }
        __syncthreads();

        if (t + 1 < ntiles) {
            int kb = kbase + 64;
#pragma unroll
            for (int i = 0; i < 8; i++) {
                int id = tid + i * 256;
                int row = id >> 3, ch = id & 7;
                cp16(sb + oVh + row * (VST * 2) + ch * 16, gVh + (size_t)row * (SEQ * 2) + kb * 2 + ch * 16);
                cp16(sb + oVl + row * (VST * 2) + ch * 16, gVl + (size_t)row * (SEQ * 2) + kb * 2 + ch * 16);
            }
            asm volatile("cp.async.commit_group;" ::: "memory");
            asm volatile("cp.async.wait_group %0;" :: "n"(1) : "memory");
        }
        __syncthreads();
    }

    const float inv0 = 1.0f / lrow[r0];
    const float inv1 = 1.0f / lrow[r1];
    const size_t row0 = (size_t)(b * SEQ + q0 + r0) * QCOLS;
    const size_t row1 = (size_t)(b * SEQ + q0 + r1) * QCOLS;
#pragma unroll
    for (int nt = 0; nt < 16; nt++) {
        const int col = h * HDIM + wh * 128 + nt * 8 + (lane & 3) * 2;
        float v0 = oacc[nt][0] * inv0, v1 = oacc[nt][1] * inv0;
        float v2 = oacc[nt][2] * inv1, v3 = oacc[nt][3] * inv1;
        __nv_bfloat16 h0 = __float2bfloat16(v0), h1 = __float2bfloat16(v1);
        __nv_bfloat16 h2 = __float2bfloat16(v2), h3 = __float2bfloat16(v3);
        *(__nv_bfloat162*)(Ch + row0 + col) = __halves2bfloat162(h0, h1);
        *(__nv_bfloat162*)(Ch + row1 + col) = __halves2bfloat162(h2, h3);
        *(__nv_bfloat162*)(Cl + row0 + col) =
            __halves2bfloat162(__float2bfloat16(v0 - __bfloat162float(h0)),
                               __float2bfloat16(v1 - __bfloat162float(h1)));
        *(__nv_bfloat162*)(Cl + row1 + col) =
            __halves2bfloat162(__float2bfloat16(v2 - __bfloat162float(h2)),
                               __float2bfloat16(v3 - __bfloat162float(h3)));
    }
}

// ---------------------------------------------------------------------------
// launch
// ---------------------------------------------------------------------------
extern "C" void kernel_launch(void* const* d_in, const int* in_sizes, int n_in,
                              void* d_out, int out_size)
{
    const float* hid = (const float*)d_in[0];
    const float* Wq  = (const float*)d_in[1];
    const float* Wk  = (const float*)d_in[2];
    const float* Wv  = (const float*)d_in[3];
    const float* Wo  = (const float*)d_in[4];
    float* out = (float*)d_out;

    float *Vb;
    cudaGetSymbolAddress((void**)&Vb, g_V);

    __nv_bfloat16 *Hh, *Hl, *WpH, *WpL, *WotH, *WotL;
    __nv_bfloat16 *Ch, *Cl, *Qh, *Ql, *Kh, *Kl, *VtH, *VtL;
    cudaGetSymbolAddress((void**)&Hh,   g_Hh);
    cudaGetSymbolAddress((void**)&Hl,   g_Hl);
    cudaGetSymbolAddress((void**)&WpH,  g_WpH);
    cudaGetSymbolAddress((void**)&WpL,  g_WpL);
    cudaGetSymbolAddress((void**)&WotH, g_WotH);
    cudaGetSymbolAddress((void**)&WotL, g_WotL);
    cudaGetSymbolAddress((void**)&Ch,   g_Ch);
    cudaGetSymbolAddress((void**)&Cl,   g_Cl);
    cudaGetSymbolAddress((void**)&Qh,   g_Qh);
    cudaGetSymbolAddress((void**)&Ql,   g_Ql);
    cudaGetSymbolAddress((void**)&Kh,   g_Kh);
    cudaGetSymbolAddress((void**)&Kl,   g_Kl);
    cudaGetSymbolAddress((void**)&VtH,  g_VtH);
    cudaGetSymbolAddress((void**)&VtL,  g_VtL);

    cudaFuncSetAttribute(gemm_mma_kernel, cudaFuncAttributeMaxDynamicSharedMemorySize,
                         GEMM_SMEM);
    cudaFuncSetAttribute(attn_tc_kernel, cudaFuncAttributeMaxDynamicSharedMemorySize,
                         ATTN_SMEM);

    rope_tables_kernel<<<(SEQ * 128 + 255) / 256, 256>>>();

    // splits / transposes of inputs (Q/K permuted for RoPE-fused epilogue)
    split_kernel<<<(MROWS * EMBED / 4 + 255) / 256, 256>>>(hid, Hh, Hl, MROWS * EMBED / 4);
    tsplit_kernel<<<dim3(QCOLS / 32, EMBED / 32), dim3(32, 8)>>>(Wq, WpH, WpL, EMBED, QCOLS, 1, 0);
    tsplit_kernel<<<dim3(KCOLS / 32, EMBED / 32), dim3(32, 8)>>>(Wk, WpH, WpL, EMBED, KCOLS, 1, QCOLS);
    tsplit_kernel<<<dim3(KCOLS / 32, EMBED / 32), dim3(32, 8)>>>(Wv, WpH, WpL, EMBED, KCOLS, 0, QCOLS + KCOLS);
    tsplit_kernel<<<dim3(EMBED / 32, QCOLS / 32), dim3(32, 8)>>>(Wo, WotH, WotL, QCOLS, EMBED, 0, 0);

    // fused QKV projection: RoPE+split epilogue for Q/K, fp32 for V
    gemm_mma_kernel<<<dim3((NPACK / 128) * (MROWS / 128)), 256, GEMM_SMEM>>>(
        Hh, Hl, WpH, WpL, nullptr, MROWS, NPACK, EMBED,
        1, Qh, Ql, Kh, Kl, Vb);

    // V transpose+split
    vtsplit_kernel<<<dim3(SEQ / 32, KCOLS / 32, BATCH), dim3(32, 8)>>>(Vb, VtH, VtL);

    // tensor-core attention -> Ch/Cl bf16 splits
    attn_tc_kernel<<<dim3(SEQ / 64, BATCH * NH), 256, ATTN_SMEM>>>(
        Qh, Ql, Kh, Kl, VtH, VtL, Ch, Cl);

    // output projection straight into d_out
    gemm_mma_kernel<<<dim3((EMBED / 128) * (MROWS / 128)), 256, GEMM_SMEM>>>(
        Ch, Cl, WotH, WotL, out, MROWS, EMBED, QCOLS,
        0, nullptr, nullptr, nullptr, nullptr, nullptr);
}

// round 14
// speedup vs baseline: 1.3964x; 1.3809x over previous
#include <cuda_runtime.h>
#include <cuda_fp16.h>
#include <math.h>
#include <stdint.h>

// ---------------------------------------------------------------------------
// Problem constants
// ---------------------------------------------------------------------------
#define BATCH   2
#define SEQ     2048
#define EMBED   3584
#define NH      16
#define NKV     8
#define HDIM    256
#define MROWS   (BATCH*SEQ)          // 4096
#define QCOLS   (NH*HDIM)            // 4096
#define KCOLS   (NKV*HDIM)           // 2048
#define NPACK   (QCOLS + 2*KCOLS)    // 8192 packed QKV columns
#define WINDOW  1024

// ---------------------------------------------------------------------------
// Static device scratch (no cudaMalloc allowed)
// ---------------------------------------------------------------------------
__device__ float g_V  [(size_t)MROWS*KCOLS];
__device__ float g_cos[SEQ*(HDIM/2)];
__device__ float g_sin[SEQ*(HDIM/2)];

// fp16 operands: A-side split hi/lo (exact), B-side single
__device__ __half g_Hh [(size_t)MROWS*EMBED];
__device__ __half g_Hl [(size_t)MROWS*EMBED];
__device__ __half g_WpH[(size_t)NPACK*EMBED];    // packed Wq|Wk|Wv, transposed, single fp16
__device__ __half g_WotH[(size_t)EMBED*QCOLS];   // Wo transposed, single fp16
__device__ __half g_Ch [(size_t)MROWS*QCOLS];
__device__ __half g_Cl [(size_t)MROWS*QCOLS];

// attention operands
__device__ __half g_Qh [(size_t)MROWS*QCOLS];
__device__ __half g_Ql [(size_t)MROWS*QCOLS];
__device__ __half g_Kh [(size_t)MROWS*KCOLS];    // single fp16 (B side)
__device__ __half g_VtH[(size_t)MROWS*KCOLS];    // per-batch transposed [KCOLS][SEQ], single

// ---------------------------------------------------------------------------
// PTX helpers (sm_100-safe)
// ---------------------------------------------------------------------------
__device__ __forceinline__ uint32_t smem_u32(const void* p) {
    uint32_t a;
    asm("{ .reg .u64 t; cvta.to.shared.u64 t, %1; cvt.u32.u64 %0, t; }" : "=r"(a) : "l"(p));
    return a;
}
__device__ __forceinline__ void cp16(uint32_t dst, const void* src) {
    asm volatile("cp.async.cg.shared.global [%0], [%1], 16;" :: "r"(dst), "l"(src) : "memory");
}
__device__ __forceinline__ void ldmx4(uint32_t* r, uint32_t addr) {
    asm volatile("ldmatrix.sync.aligned.m8n8.x4.shared.b16 {%0,%1,%2,%3}, [%4];"
                 : "=r"(r[0]), "=r"(r[1]), "=r"(r[2]), "=r"(r[3]) : "r"(addr));
}
__device__ __forceinline__ void mma_f16(float* c, const uint32_t* a,
                                        uint32_t b0, uint32_t b1) {
    asm volatile(
        "mma.sync.aligned.m16n8k16.row.col.f32.f16.f16.f32 "
        "{%0,%1,%2,%3}, {%4,%5,%6,%7}, {%8,%9}, {%0,%1,%2,%3};"
        : "+f"(c[0]), "+f"(c[1]), "+f"(c[2]), "+f"(c[3])
        : "r"(a[0]), "r"(a[1]), "r"(a[2]), "r"(a[3]), "r"(b0), "r"(b1));
}

// FMA-pipe exp (no MUFU): e^x for |x| <= ~85, rel err ~1.5e-7
__device__ __forceinline__ float fexp(float x) {
    float y  = x * 1.4426950408889634f;
    float fm = y + 12582912.0f;
    float nf = fm - 12582912.0f;
    float f  = y - nf;
    int   sc = ((__float_as_int(fm) - 0x4B400000) + 127) << 23;
    float t  = f * 0.6931471805599453f;
    float p  = 1.0f + t*(1.0f + t*(0.5f + t*(0.16666667f +
               t*(0.041666667f + t*(0.008333334f + t*0.0013888889f)))));
    return p * __int_as_float(sc);
}
// FMA-pipe reciprocal (bit-hack + 3 Newton)
__device__ __forceinline__ float frcp(float d) {
    float r = __int_as_float(0x7EF311C3 - __float_as_int(d));
    r = r * (2.0f - d * r);
    r = r * (2.0f - d * r);
    r = r * (2.0f - d * r);
    return r;
}

// ---------------------------------------------------------------------------
// fp32 -> fp16 hi/lo split (vectorized)
// ---------------------------------------------------------------------------
__global__ void split_kernel(const float* __restrict__ in,
                             __half* __restrict__ hi,
                             __half* __restrict__ lo, int n4)
{
    int i = blockIdx.x * 256 + threadIdx.x;
    if (i >= n4) return;
    float4 v = ((const float4*)in)[i];
    __half h0 = __float2half(v.x);
    __half h1 = __float2half(v.y);
    __half h2 = __float2half(v.z);
    __half h3 = __float2half(v.w);
    __half l0 = __float2half(v.x - __half2float(h0));
    __half l1 = __float2half(v.y - __half2float(h1));
    __half l2 = __float2half(v.z - __half2float(h2));
    __half l3 = __float2half(v.w - __half2float(h3));
    ((__half2*)hi)[2*i]   = __halves2half2(h0, h1);
    ((__half2*)hi)[2*i+1] = __halves2half2(h2, h3);
    ((__half2*)lo)[2*i]   = __halves2half2(l0, l1);
    ((__half2*)lo)[2*i+1] = __halves2half2(l2, l3);
}

// ---------------------------------------------------------------------------
// Transpose (+optional RoPE-pair perm): W [K,N] fp32 -> Th [rowoff+perm(n)][K] fp16
// ---------------------------------------------------------------------------
__global__ void tsplit_kernel(const float* __restrict__ W,
                              __half* __restrict__ Th, int K, int N,
                              int perm, int rowoff)
{
    __shared__ float t[32][33];
    int n0 = blockIdx.x * 32, k0 = blockIdx.y * 32;
    int tx = threadIdx.x, ty = threadIdx.y;
#pragma unroll
    for (int i = 0; i < 32; i += 8)
        t[ty + i][tx] = W[(size_t)(k0 + ty + i) * N + n0 + tx];
    __syncthreads();
#pragma unroll
    for (int i = 0; i < 32; i += 8) {
        float v = t[tx][ty + i];
        int n = n0 + ty + i;
        int nb = n & 255;
        int np = perm ? ((n & ~255) + ((nb < 128) ? (nb << 1) : (((nb - 128) << 1) | 1)))
                      : n;
        Th[(size_t)(rowoff + np) * K + k0 + tx] = __float2half(v);
    }
}

// ---------------------------------------------------------------------------
// V transpose per batch: g_V [b*SEQ+s][KCOLS] -> Vt [b][KCOLS][SEQ] fp16
// ---------------------------------------------------------------------------
__global__ void vtsplit_kernel(const float* __restrict__ V,
                               __half* __restrict__ Th)
{
    __shared__ float t[32][33];
    int s0 = blockIdx.x * 32, c0 = blockIdx.y * 32, b = blockIdx.z;
    int tx = threadIdx.x, ty = threadIdx.y;
#pragma unroll
    for (int i = 0; i < 32; i += 8)
        t[ty + i][tx] = V[((size_t)b * SEQ + s0 + ty + i) * KCOLS + c0 + tx];
    __syncthreads();
#pragma unroll
    for (int i = 0; i < 32; i += 8) {
        float v = t[tx][ty + i];
        size_t o = ((size_t)b * KCOLS + c0 + ty + i) * SEQ + s0 + tx;
        Th[o] = __float2half(v);
    }
}

// ---------------------------------------------------------------------------
// RoPE tables (double precision)
// ---------------------------------------------------------------------------
__global__ void rope_tables_kernel()
{
    int idx = blockIdx.x * 256 + threadIdx.x;
    if (idx >= SEQ * (HDIM / 2)) return;
    int i = idx & 127;
    int pos = idx >> 7;
    double invf = pow(10000.0, -(double)(2 * i) / (double)HDIM);
    double ang = (double)pos * invf;
    g_cos[idx] = (float)cos(ang);
    g_sin[idx] = (float)sin(ang);
}

// ---------------------------------------------------------------------------
// mma.sync fp16x2 GEMM: C = (Ah+Al)[M,K] @ Bh[N,K]^T, 3-stage pipeline,
// 2 CTAs/SM, supertile rasterization (GSW n-tiles per column).
// mode 0: plain fp32 C. mode 1: fused QKV (RoPE epilogue Q->h/l, K->single,
// V segment -> Vb fp32).
// ---------------------------------------------------------------------------
#define GKC       32
#define GSTRIDE   40
#define GTILE_B   (128*GSTRIDE*2)    // 10240 B per tile
#define GSTAGE_B  (3*GTILE_B)        // Ah, Al, Bh = 30720 B
#define GEMM_SMEM (3*GSTAGE_B)       // 92160 B -> 2 CTAs/SM (184320 <= 227KB)
#define GSW       16

__device__ __forceinline__ void fill_stage(uint32_t stb,
                                           const __half* Ah0,
                                           const __half* Al0,
                                           const __half* Bh0,
                                           int K, int tid)
{
    const __half* srcs[3] = {Ah0, Al0, Bh0};
#pragma unroll
    for (int t = 0; t < 3; t++) {
        uint32_t tb = stb + t * GTILE_B;
        const char* s = (const char*)srcs[t];
#pragma unroll
        for (int i = 0; i < 2; i++) {
            int id = tid + i * 256;
            int row = id >> 2, ch = id & 3;
            cp16(tb + row * (GSTRIDE * 2) + ch * 16,
                 s + (size_t)row * K * 2 + ch * 16);
        }
    }
    asm volatile("cp.async.commit_group;" ::: "memory");
}

__global__ void __launch_bounds__(256, 2)
gemm_mma_kernel(const __half* __restrict__ Ah,
                const __half* __restrict__ Al,
                const __half* __restrict__ Bh,
                float* __restrict__ C, int M, int N, int K,
                int fused,
                __half* __restrict__ Qh, __half* __restrict__ Ql,
                __half* __restrict__ Kh,
                float* __restrict__ Vb)
{
    extern __shared__ char gsm[];
    const uint32_t sbase = smem_u32(gsm);
    const int tid = threadIdx.x;
    const int wid = tid >> 5, lane = tid & 31;
    const int wm = wid & 1, wn = wid >> 1;

    // supertile rasterization
    const int Mt = M >> 7, Ntl = N >> 7;
    int mtile, ntile;
    {
        const int bid = blockIdx.x;
        const int per = GSW * Mt;
        const int fullcols = Ntl / GSW;
        if (bid < fullcols * per) {
            const int col = bid / per;
            const int r = bid % per;
            mtile = r / GSW;
            ntile = col * GSW + r % GSW;
        } else {
            const int r = bid - fullcols * per;
            const int wdt = Ntl - fullcols * GSW;
            mtile = r / wdt;
            ntile = fullcols * GSW + r % wdt;
        }
    }
    const int m0 = mtile * 128, n0 = ntile * 128;

    uint32_t a_off[4], b_off[2];
#pragma unroll
    for (int mt = 0; mt < 4; mt++)
        a_off[mt] = ((wm * 64 + mt * 16 + (lane & 15)) * GSTRIDE
                     + (lane >> 4) * 8) * 2;
#pragma unroll
    for (int np = 0; np < 2; np++)
        b_off[np] = ((wn * 32 + np * 16 + (lane & 7) + ((lane >> 4) & 1) * 8) * GSTRIDE
                     + ((lane >> 3) & 1) * 8) * 2;

    const __half* Ah0 = Ah + (size_t)m0 * K;
    const __half* Al0 = Al + (size_t)m0 * K;
    const __half* Bh0 = Bh + (size_t)n0 * K;

    float acc[4][4][4];
#pragma unroll
    for (int mt = 0; mt < 4; mt++)
#pragma unroll
        for (int nt = 0; nt < 4; nt++)
#pragma unroll
            for (int r = 0; r < 4; r++) acc[mt][nt][r] = 0.f;

    const int NC = K / GKC;

    // prologue: 3 stages in flight
#pragma unroll
    for (int c = 0; c < 3; c++)
        fill_stage(sbase + c * GSTAGE_B, Ah0 + c * GKC, Al0 + c * GKC,
                   Bh0 + c * GKC, K, tid);

    for (int c = 0; c < NC; c++) {
        const uint32_t stb = sbase + (c % 3) * GSTAGE_B;
        asm volatile("cp.async.wait_group %0;" :: "n"(2) : "memory");
        __syncthreads();

#pragma unroll
        for (int ks = 0; ks < 2; ks++) {
            const uint32_t ko = ks * 32;
            uint32_t ax[4][4], bx[2][4];

            // load Ah + Bh
#pragma unroll
            for (int mt = 0; mt < 4; mt++) ldmx4(ax[mt], stb + 0 * GTILE_B + a_off[mt] + ko);
#pragma unroll
            for (int np = 0; np < 2; np++) ldmx4(bx[np], stb + 2 * GTILE_B + b_off[np] + ko);

            // term 1: Ah * B
#pragma unroll
            for (int mt = 0; mt < 4; mt++)
#pragma unroll
                for (int nt = 0; nt < 4; nt++) {
                    const int np = nt >> 1, bi = (nt & 1) * 2;
                    mma_f16(acc[mt][nt], ax[mt], bx[np][bi], bx[np][bi + 1]);
                }

            // term 2: Al * B (B resident)
#pragma unroll
            for (int mt = 0; mt < 4; mt++) ldmx4(ax[mt], stb + 1 * GTILE_B + a_off[mt] + ko);
#pragma unroll
            for (int mt = 0; mt < 4; mt++)
#pragma unroll
                for (int nt = 0; nt < 4; nt++) {
                    const int np = nt >> 1, bi = (nt & 1) * 2;
                    mma_f16(acc[mt][nt], ax[mt], bx[np][bi], bx[np][bi + 1]);
                }
        }

        __syncthreads();
        const int cn = c + 3;
        if (cn < NC)
            fill_stage(stb, Ah0 + cn * GKC, Al0 + cn * GKC,
                       Bh0 + cn * GKC, K, tid);
    }

    const int rr = lane >> 2, cc = (lane & 3) * 2;

    if (!fused) {
#pragma unroll
        for (int mt = 0; mt < 4; mt++) {
            const size_t mA = (size_t)(m0 + wm * 64 + mt * 16 + rr);
#pragma unroll
            for (int nt = 0; nt < 4; nt++) {
                const int n = n0 + wn * 32 + nt * 8 + cc;
                *(float2*)(C + mA * N + n) =
                    make_float2(acc[mt][nt][0], acc[mt][nt][1]);
                *(float2*)(C + (mA + 8) * N + n) =
                    make_float2(acc[mt][nt][2], acc[mt][nt][3]);
            }
        }
        return;
    }

    if (n0 >= QCOLS + KCOLS) {
        // V segment: fp32 into Vb (stride KCOLS)
#pragma unroll
        for (int mt = 0; mt < 4; mt++) {
            const size_t mA = (size_t)(m0 + wm * 64 + mt * 16 + rr);
#pragma unroll
            for (int nt = 0; nt < 4; nt++) {
                const int n = (n0 - (QCOLS + KCOLS)) + wn * 32 + nt * 8 + cc;
                *(float2*)(Vb + mA * KCOLS + n) =
                    make_float2(acc[mt][nt][0], acc[mt][nt][1]);
                *(float2*)(Vb + (mA + 8) * KCOLS + n) =
                    make_float2(acc[mt][nt][2], acc[mt][nt][3]);
            }
        }
        return;
    }

    // Q or K segment: RoPE, then Q -> h/l split, K -> single fp16
    const int isQ = (n0 < QCOLS);
    const int xs = isQ ? QCOLS : KCOLS;
    const int segbase = isQ ? 0 : QCOLS;

#pragma unroll
    for (int mt = 0; mt < 4; mt++) {
        const int mA = m0 + wm * 64 + mt * 16 + rr;
#pragma unroll
        for (int nt = 0; nt < 4; nt++) {
            const int colp = (n0 - segbase) + wn * 32 + nt * 8 + cc; // even
            const int head = colp >> 8;
            const int i    = (colp & 255) >> 1;
            const int ca   = head * 256 + i;
            const int cb   = ca + 128;
#pragma unroll
            for (int rh = 0; rh < 2; rh++) {
                const int m   = mA + rh * 8;
                const int pos = m & (SEQ - 1);
                const float co = g_cos[pos * 128 + i];
                const float si = g_sin[pos * 128 + i];
                const float x1 = acc[mt][nt][rh * 2 + 0];
                const float x2 = acc[mt][nt][rh * 2 + 1];
                const float y1 = x1 * co - x2 * si;
                const float y2 = x2 * co + x1 * si;
                const size_t rb = (size_t)m * xs;
                if (isQ) {
                    const __half h1 = __float2half(y1);
                    const __half h2 = __float2half(y2);
                    Qh[rb + ca] = h1;
                    Qh[rb + cb] = h2;
                    Ql[rb + ca] = __float2half(y1 - __half2float(h1));
                    Ql[rb + cb] = __float2half(y2 - __half2float(h2));
                } else {
                    Kh[rb + ca] = __float2half(y1);
                    Kh[rb + cb] = __float2half(y2);
                }
            }
        }
    }
}

// ---------------------------------------------------------------------------
// Tensor-core flash attention, fp16x2 (Q exact x K single; P exact x V single),
// no-max softmax (|logit| <= 50), FMA-pipe exp/rcp.
// ---------------------------------------------------------------------------
#define DST 264   // Q/K smem row stride (fp16)
#define VST 72
#define PST 72
#define oQh 0
#define oQl 33792
#define oKh 67584
#define oVh 101376
#define oPh 138240
#define oPl 147456
#define oLrow 156672
#define ATTN_SMEM (156672 + 256)

__global__ void __launch_bounds__(256, 1)
attn_tc_kernel(const __half* __restrict__ Qh, const __half* __restrict__ Ql,
               const __half* __restrict__ Kh,
               const __half* __restrict__ Vth,
               __half* __restrict__ Ch, __half* __restrict__ Cl)
{
    extern __shared__ char smraw[];
    const uint32_t sb = smem_u32(smraw);
    float* lrow = (float*)(smraw + oLrow);

    const int tid = threadIdx.x;
    const int wid = tid >> 5, lane = tid & 31;
    const int wq = wid & 3, wh = wid >> 2;
    const int b  = blockIdx.y >> 4;
    const int h  = blockIdx.y & 15;
    const int kvh = h >> 1;
    const int q0 = blockIdx.x * 64;

    const char* gQh = (const char*)(Qh + ((size_t)(b * SEQ + q0)) * QCOLS + h * HDIM);
    const char* gQl = (const char*)(Ql + ((size_t)(b * SEQ + q0)) * QCOLS + h * HDIM);
    const char* gKh = (const char*)(Kh + ((size_t)(b * SEQ)) * KCOLS + kvh * HDIM);
    const char* gVh = (const char*)(Vth + ((size_t)(b * KCOLS + kvh * HDIM)) * SEQ);

    if (tid < 64) lrow[tid] = 0.f;

    int klo = q0 - WINDOW;       if (klo < 0) klo = 0;
    int khi = q0 + 64 + WINDOW;  if (khi > SEQ) khi = SEQ;
    const int kt0 = klo >> 6;
    const int ntiles = (khi >> 6) - kt0;

    // prologue: Q h/l + K(0) [group], V(0) [group]
#pragma unroll
    for (int i = 0; i < 8; i++) {
        int id = tid + i * 256;
        int row = id >> 5, ch = id & 31;
        cp16(sb + oQh + row * (DST * 2) + ch * 16, gQh + (size_t)row * (QCOLS * 2) + ch * 16);
        cp16(sb + oQl + row * (DST * 2) + ch * 16, gQl + (size_t)row * (QCOLS * 2) + ch * 16);
    }
    {
        int kb = kt0 * 64;
#pragma unroll
        for (int i = 0; i < 8; i++) {
            int id = tid + i * 256;
            int row = id >> 5, ch = id & 31;
            cp16(sb + oKh + row * (DST * 2) + ch * 16, gKh + (size_t)(kb + row) * (KCOLS * 2) + ch * 16);
        }
        asm volatile("cp.async.commit_group;" ::: "memory");
#pragma unroll
        for (int i = 0; i < 8; i++) {
            int id = tid + i * 256;
            int row = id >> 3, ch = id & 7;
            cp16(sb + oVh + row * (VST * 2) + ch * 16, gVh + (size_t)row * (SEQ * 2) + kb * 2 + ch * 16);
        }
        asm volatile("cp.async.commit_group;" ::: "memory");
    }
    asm volatile("cp.async.wait_group %0;" :: "n"(1) : "memory");
    __syncthreads();

    const uint32_t a_off = ((wq * 16 + (lane & 15)) * DST + (lane >> 4) * 8) * 2;
    uint32_t bs_off[2];
#pragma unroll
    for (int np = 0; np < 2; np++)
        bs_off[np] = ((wh * 32 + np * 16 + (lane & 7) + ((lane >> 4) & 1) * 8) * DST
                      + ((lane >> 3) & 1) * 8) * 2;
    const uint32_t ap_off = ((wq * 16 + (lane & 15)) * PST + (lane >> 4) * 8) * 2;
    uint32_t bv_off[8];
#pragma unroll
    for (int np = 0; np < 8; np++)
        bv_off[np] = ((wh * 128 + np * 16 + (lane & 7) + ((lane >> 4) & 1) * 8) * VST
                      + ((lane >> 3) & 1) * 8) * 2;

    float oacc[16][4];
#pragma unroll
    for (int nt = 0; nt < 16; nt++)
#pragma unroll
        for (int r = 0; r < 4; r++) oacc[nt][r] = 0.f;

    const int r0 = wq * 16 + (lane >> 2), r1 = r0 + 8;
    const int qg0 = q0 + r0, qg1 = q0 + r1;

    for (int t = 0; t < ntiles; t++) {
        const int kbase = (kt0 + t) * 64;

        // ---- S = (Qh+Ql) K^T ----
        float sacc[4][4];
#pragma unroll
        for (int nt = 0; nt < 4; nt++)
#pragma unroll
            for (int r = 0; r < 4; r++) sacc[nt][r] = 0.f;

#pragma unroll 4
        for (int ks = 0; ks < 16; ks++) {
            const uint32_t ko = ks * 32;
            uint32_t qhf[4], qlf[4], khf[2][4];
            ldmx4(qhf, sb + oQh + a_off + ko);
            ldmx4(qlf, sb + oQl + a_off + ko);
#pragma unroll
            for (int np = 0; np < 2; np++)
                ldmx4(khf[np], sb + oKh + bs_off[np] + ko);
#pragma unroll
            for (int nt = 0; nt < 4; nt++) {
                const int np = nt >> 1, bi = (nt & 1) * 2;
                mma_f16(sacc[nt], qhf, khf[np][bi], khf[np][bi + 1]);
                mma_f16(sacc[nt], qlf, khf[np][bi], khf[np][bi + 1]);
            }
        }

        // ---- soft-cap + window mask + exp, write P splits ----
        float psum0 = 0.f, psum1 = 0.f;
#pragma unroll
        for (int nt = 0; nt < 4; nt++) {
            const int cl = wh * 32 + nt * 8 + (lane & 3) * 2;
            const int cg = kbase + cl;
            float p[4];
#pragma unroll
            for (int e = 0; e < 4; e++) {
                const int qg = (e < 2) ? qg0 : qg1;
                const int kg = cg + (e & 1);
                int dlt = qg - kg; if (dlt < 0) dlt = -dlt;
                if (dlt <= WINDOW) {
                    float E = fexp(sacc[nt][e] * 0.0025f);
                    float l = fmaf(-100.f, frcp(E + 1.f), 50.f);
                    p[e] = fexp(l);
                } else p[e] = 0.f;
            }
            psum0 += p[0] + p[1];
            psum1 += p[2] + p[3];
            __half h0 = __float2half(p[0]), h1 = __float2half(p[1]);
            __half h2 = __float2half(p[2]), h3 = __float2half(p[3]);
            *(__half2*)(smraw + oPh + (r0 * PST + cl) * 2) = __halves2half2(h0, h1);
            *(__half2*)(smraw + oPh + (r1 * PST + cl) * 2) = __halves2half2(h2, h3);
            *(__half2*)(smraw + oPl + (r0 * PST + cl) * 2) =
                __halves2half2(__float2half(p[0] - __half2float(h0)),
                               __float2half(p[1] - __half2float(h1)));
            *(__half2*)(smraw + oPl + (r1 * PST + cl) * 2) =
                __halves2half2(__float2half(p[2] - __half2float(h2)),
                               __float2half(p[3] - __half2float(h3)));
        }
        psum0 += __shfl_xor_sync(0xffffffffu, psum0, 1);
        psum0 += __shfl_xor_sync(0xffffffffu, psum0, 2);
        psum1 += __shfl_xor_sync(0xffffffffu, psum1, 1);
        psum1 += __shfl_xor_sync(0xffffffffu, psum1, 2);
        if ((lane & 3) == 0) {
            atomicAdd(&lrow[r0], psum0);
            atomicAdd(&lrow[r1], psum1);
        }

        asm volatile("cp.async.wait_group %0;" :: "n"(0) : "memory");
        __syncthreads();

        if (t + 1 < ntiles) {                 // prefetch K(t+1)
            int kb = kbase + 64;
#pragma unroll
            for (int i = 0; i < 8; i++) {
                int id = tid + i * 256;
                int row = id >> 5, ch = id & 31;
                cp16(sb + oKh + row * (DST * 2) + ch * 16, gKh + (size_t)(kb + row) * (KCOLS * 2) + ch * 16);
            }
            asm volatile("cp.async.commit_group;" ::: "memory");
        }

        // ---- O += (Ph+Pl) V ----
#pragma unroll
        for (int kp = 0; kp < 4; kp++) {
            const uint32_t ko = kp * 32;
            uint32_t pah[4], pal[4];
            ldmx4(pah, sb + oPh + ap_off + ko);
            ldmx4(pal, sb + oPl + ap_off + ko);
#pragma unroll
            for (int np = 0; np < 8; np++) {
                uint32_t vbh[4];
                ldmx4(vbh, sb + oVh + bv_off[np] + ko);
#pragma unroll
                for (int i = 0; i < 2; i++) {
                    const int nt = np * 2 + i, bi = i * 2;
                    mma_f16(oacc[nt], pah, vbh[bi], vbh[bi + 1]);
                    mma_f16(oacc[nt], pal, vbh[bi], vbh[bi + 1]);
                }
            }
        }
        __syncthreads();

        if (t + 1 < ntiles) {                 // prefetch V(t+1)
            int kb = kbase + 64;
#pragma unroll
            for (int i = 0; i < 8; i++) {
                int id = tid + i * 256;
                int row = id >> 3, ch = id & 7;
                cp16(sb + oVh + row * (VST * 2) + ch * 16, gVh + (size_t)row * (SEQ * 2) + kb * 2 + ch * 16);
            }
            asm volatile("cp.async.commit_group;" ::: "memory");
            asm volatile("cp.async.wait_group %0;" :: "n"(1) : "memory");
        }
        __syncthreads();
    }

    // ---- normalize, split to fp16 h/l, write context ----
    const float inv0 = 1.0f / lrow[r0];
    const float inv1 = 1.0f / lrow[r1];
    const size_t row0 = (size_t)(b * SEQ + q0 + r0) * QCOLS;
    const size_t row1 = (size_t)(b * SEQ + q0 + r1) * QCOLS;
#pragma unroll
    for (int nt = 0; nt < 16; nt++) {
        const int col = h * HDIM + wh * 128 + nt * 8 + (lane & 3) * 2;
        float v0 = oacc[nt][0] * inv0, v1 = oacc[nt][1] * inv0;
        float v2 = oacc[nt][2] * inv1, v3 = oacc[nt][3] * inv1;
        __half h0 = __float2half(v0), h1 = __float2half(v1);
        __half h2 = __float2half(v2), h3 = __float2half(v3);
        *(__half2*)(Ch + row0 + col) = __halves2half2(h0, h1);
        *(__half2*)(Ch + row1 + col) = __halves2half2(h2, h3);
        *(__half2*)(Cl + row0 + col) =
            __halves2half2(__float2half(v0 - __half2float(h0)),
                           __float2half(v1 - __half2float(h1)));
        *(__half2*)(Cl + row1 + col) =
            __halves2half2(__float2half(v2 - __half2float(h2)),
                           __float2half(v3 - __half2float(h3)));
    }
}

// ---------------------------------------------------------------------------
// launch
// ---------------------------------------------------------------------------
extern "C" void kernel_launch(void* const* d_in, const int* in_sizes, int n_in,
                              void* d_out, int out_size)
{
    const float* hid = (const float*)d_in[0];
    const float* Wq  = (const float*)d_in[1];
    const float* Wk  = (const float*)d_in[2];
    const float* Wv  = (const float*)d_in[3];
    const float* Wo  = (const float*)d_in[4];
    float* out = (float*)d_out;

    float *Vb;
    cudaGetSymbolAddress((void**)&Vb, g_V);

    __half *Hh, *Hl, *WpH, *WotH, *Ch, *Cl, *Qh, *Ql, *Kh, *VtH;
    cudaGetSymbolAddress((void**)&Hh,   g_Hh);
    cudaGetSymbolAddress((void**)&Hl,   g_Hl);
    cudaGetSymbolAddress((void**)&WpH,  g_WpH);
    cudaGetSymbolAddress((void**)&WotH, g_WotH);
    cudaGetSymbolAddress((void**)&Ch,   g_Ch);
    cudaGetSymbolAddress((void**)&Cl,   g_Cl);
    cudaGetSymbolAddress((void**)&Qh,   g_Qh);
    cudaGetSymbolAddress((void**)&Ql,   g_Ql);
    cudaGetSymbolAddress((void**)&Kh,   g_Kh);
    cudaGetSymbolAddress((void**)&VtH,  g_VtH);

    cudaFuncSetAttribute(gemm_mma_kernel, cudaFuncAttributeMaxDynamicSharedMemorySize,
                         GEMM_SMEM);
    cudaFuncSetAttribute(attn_tc_kernel, cudaFuncAttributeMaxDynamicSharedMemorySize,
                         ATTN_SMEM);

    rope_tables_kernel<<<(SEQ * 128 + 255) / 256, 256>>>();

    // preprocessing (Q/K cols permuted for RoPE-fused epilogue)
    split_kernel<<<(MROWS * EMBED / 4 + 255) / 256, 256>>>(hid, Hh, Hl, MROWS * EMBED / 4);
    tsplit_kernel<<<dim3(QCOLS / 32, EMBED / 32), dim3(32, 8)>>>(Wq, WpH, EMBED, QCOLS, 1, 0);
    tsplit_kernel<<<dim3(KCOLS / 32, EMBED / 32), dim3(32, 8)>>>(Wk, WpH, EMBED, KCOLS, 1, QCOLS);
    tsplit_kernel<<<dim3(KCOLS / 32, EMBED / 32), dim3(32, 8)>>>(Wv, WpH, EMBED, KCOLS, 0, QCOLS + KCOLS);
    tsplit_kernel<<<dim3(EMBED / 32, QCOLS / 32), dim3(32, 8)>>>(Wo, WotH, QCOLS, EMBED, 0, 0);

    // fused QKV projection
    gemm_mma_kernel<<<dim3((NPACK / 128) * (MROWS / 128)), 256, GEMM_SMEM>>>(
        Hh, Hl, WpH, nullptr, MROWS, NPACK, EMBED,
        1, Qh, Ql, Kh, Vb);

    // V transpose
    vtsplit_kernel<<<dim3(SEQ / 32, KCOLS / 32, BATCH), dim3(32, 8)>>>(Vb, VtH);

    // attention -> Ch/Cl fp16 splits
    attn_tc_kernel<<<dim3(SEQ / 64, BATCH * NH), 256, ATTN_SMEM>>>(
        Qh, Ql, Kh, VtH, Ch, Cl);

    // output projection straight into d_out
    gemm_mma_kernel<<<dim3((EMBED / 128) * (MROWS / 128)), 256, GEMM_SMEM>>>(
        Ch, Cl, WotH, out, MROWS, EMBED, QCOLS,
        0, nullptr, nullptr, nullptr, nullptr);
}

// round 15
// speedup vs baseline: 1.6634x; 1.1912x over previous
#include <cuda_runtime.h>
#include <cuda_fp16.h>
#include <math.h>
#include <stdint.h>

// ---------------------------------------------------------------------------
// Problem constants
// ---------------------------------------------------------------------------
#define BATCH   2
#define SEQ     2048
#define EMBED   3584
#define NH      16
#define NKV     8
#define HDIM    256
#define MROWS   (BATCH*SEQ)          // 4096
#define QCOLS   (NH*HDIM)            // 4096
#define KCOLS   (NKV*HDIM)           // 2048
#define NPACK   (QCOLS + 2*KCOLS)    // 8192 packed QKV columns
#define WINDOW  1024

// ---------------------------------------------------------------------------
// Static device scratch (no cudaMalloc allowed)
// ---------------------------------------------------------------------------
__device__ float g_V  [(size_t)MROWS*KCOLS];
__device__ float g_cos[SEQ*(HDIM/2)];
__device__ float g_sin[SEQ*(HDIM/2)];

// fp16 operands
__device__ __half g_Hh [(size_t)MROWS*EMBED];
__device__ __half g_Hl [(size_t)MROWS*EMBED];
__device__ __half g_WpH[(size_t)NPACK*EMBED];    // packed Wq|Wk|Wv, transposed
__device__ __half g_WotH[(size_t)EMBED*QCOLS];   // Wo transposed
__device__ __half g_Ch [(size_t)MROWS*QCOLS];    // attention output, single fp16

// attention operands
__device__ __half g_Qh [(size_t)MROWS*QCOLS];
__device__ __half g_Ql [(size_t)MROWS*QCOLS];
__device__ __half g_Kh [(size_t)MROWS*KCOLS];    // single fp16 (B side)
__device__ __half g_VtH[(size_t)MROWS*KCOLS];    // per-batch transposed [KCOLS][SEQ]

// ---------------------------------------------------------------------------
// PTX helpers (sm_100-safe)
// ---------------------------------------------------------------------------
__device__ __forceinline__ uint32_t smem_u32(const void* p) {
    uint32_t a;
    asm("{ .reg .u64 t; cvta.to.shared.u64 t, %1; cvt.u32.u64 %0, t; }" : "=r"(a) : "l"(p));
    return a;
}
__device__ __forceinline__ void cp16(uint32_t dst, const void* src) {
    asm volatile("cp.async.cg.shared.global [%0], [%1], 16;" :: "r"(dst), "l"(src) : "memory");
}
__device__ __forceinline__ void ldmx4(uint32_t* r, uint32_t addr) {
    asm volatile("ldmatrix.sync.aligned.m8n8.x4.shared.b16 {%0,%1,%2,%3}, [%4];"
                 : "=r"(r[0]), "=r"(r[1]), "=r"(r[2]), "=r"(r[3]) : "r"(addr));
}
__device__ __forceinline__ void mma_f16(float* c, const uint32_t* a,
                                        uint32_t b0, uint32_t b1) {
    asm volatile(
        "mma.sync.aligned.m16n8k16.row.col.f32.f16.f16.f32 "
        "{%0,%1,%2,%3}, {%4,%5,%6,%7}, {%8,%9}, {%0,%1,%2,%3};"
        : "+f"(c[0]), "+f"(c[1]), "+f"(c[2]), "+f"(c[3])
        : "r"(a[0]), "r"(a[1]), "r"(a[2]), "r"(a[3]), "r"(b0), "r"(b1));
}

// FMA-pipe exp (no MUFU): e^x for |x| <= ~85, rel err ~1.5e-7
__device__ __forceinline__ float fexp(float x) {
    float y  = x * 1.4426950408889634f;
    float fm = y + 12582912.0f;
    float nf = fm - 12582912.0f;
    float f  = y - nf;
    int   sc = ((__float_as_int(fm) - 0x4B400000) + 127) << 23;
    float t  = f * 0.6931471805599453f;
    float p  = 1.0f + t*(1.0f + t*(0.5f + t*(0.16666667f +
               t*(0.041666667f + t*(0.008333334f + t*0.0013888889f)))));
    return p * __int_as_float(sc);
}
// FMA-pipe reciprocal (bit-hack + 3 Newton)
__device__ __forceinline__ float frcp(float d) {
    float r = __int_as_float(0x7EF311C3 - __float_as_int(d));
    r = r * (2.0f - d * r);
    r = r * (2.0f - d * r);
    r = r * (2.0f - d * r);
    return r;
}

// ---------------------------------------------------------------------------
// fp32 -> fp16 hi/lo split (vectorized)
// ---------------------------------------------------------------------------
__global__ void split_kernel(const float* __restrict__ in,
                             __half* __restrict__ hi,
                             __half* __restrict__ lo, int n4)
{
    int i = blockIdx.x * 256 + threadIdx.x;
    if (i >= n4) return;
    float4 v = ((const float4*)in)[i];
    __half h0 = __float2half(v.x);
    __half h1 = __float2half(v.y);
    __half h2 = __float2half(v.z);
    __half h3 = __float2half(v.w);
    __half l0 = __float2half(v.x - __half2float(h0));
    __half l1 = __float2half(v.y - __half2float(h1));
    __half l2 = __float2half(v.z - __half2float(h2));
    __half l3 = __float2half(v.w - __half2float(h3));
    ((__half2*)hi)[2*i]   = __halves2half2(h0, h1);
    ((__half2*)hi)[2*i+1] = __halves2half2(h2, h3);
    ((__half2*)lo)[2*i]   = __halves2half2(l0, l1);
    ((__half2*)lo)[2*i+1] = __halves2half2(l2, l3);
}

// ---------------------------------------------------------------------------
// Transpose (+optional RoPE-pair perm): W [K,N] fp32 -> Th [rowoff+perm(n)][K] fp16
// ---------------------------------------------------------------------------
__global__ void tsplit_kernel(const float* __restrict__ W,
                              __half* __restrict__ Th, int K, int N,
                              int perm, int rowoff)
{
    __shared__ float t[32][33];
    int n0 = blockIdx.x * 32, k0 = blockIdx.y * 32;
    int tx = threadIdx.x, ty = threadIdx.y;
#pragma unroll
    for (int i = 0; i < 32; i += 8)
        t[ty + i][tx] = W[(size_t)(k0 + ty + i) * N + n0 + tx];
    __syncthreads();
#pragma unroll
    for (int i = 0; i < 32; i += 8) {
        float v = t[tx][ty + i];
        int n = n0 + ty + i;
        int nb = n & 255;
        int np = perm ? ((n & ~255) + ((nb < 128) ? (nb << 1) : (((nb - 128) << 1) | 1)))
                      : n;
        Th[(size_t)(rowoff + np) * K + k0 + tx] = __float2half(v);
    }
}

// ---------------------------------------------------------------------------
// V transpose per batch: g_V [b*SEQ+s][KCOLS] -> Vt [b][KCOLS][SEQ] fp16
// ---------------------------------------------------------------------------
__global__ void vtsplit_kernel(const float* __restrict__ V,
                               __half* __restrict__ Th)
{
    __shared__ float t[32][33];
    int s0 = blockIdx.x * 32, c0 = blockIdx.y * 32, b = blockIdx.z;
    int tx = threadIdx.x, ty = threadIdx.y;
#pragma unroll
    for (int i = 0; i < 32; i += 8)
        t[ty + i][tx] = V[((size_t)b * SEQ + s0 + ty + i) * KCOLS + c0 + tx];
    __syncthreads();
#pragma unroll
    for (int i = 0; i < 32; i += 8) {
        float v = t[tx][ty + i];
        size_t o = ((size_t)b * KCOLS + c0 + ty + i) * SEQ + s0 + tx;
        Th[o] = __float2half(v);
    }
}

// ---------------------------------------------------------------------------
// RoPE tables (double precision)
// ---------------------------------------------------------------------------
__global__ void rope_tables_kernel()
{
    int idx = blockIdx.x * 256 + threadIdx.x;
    if (idx >= SEQ * (HDIM / 2)) return;
    int i = idx & 127;
    int pos = idx >> 7;
    double invf = pow(10000.0, -(double)(2 * i) / (double)HDIM);
    double ang = (double)pos * invf;
    g_cos[idx] = (float)cos(ang);
    g_sin[idx] = (float)sin(ang);
}

// ---------------------------------------------------------------------------
// mma.sync fp16 GEMM: C = (Ah[+Al])[M,K] @ Bh[N,K]^T, 3-stage pipeline,
// 2 CTAs/SM, supertile rasterization. Al==nullptr -> single-term A.
// mode 0: plain fp32 C. mode 1: fused QKV (RoPE epilogue Q->h/l, K->single,
// V segment -> Vb fp32).
// ---------------------------------------------------------------------------
#define GKC       32
#define GSTRIDE   40
#define GTILE_B   (128*GSTRIDE*2)    // 10240 B per tile
#define GSTAGE_B  (3*GTILE_B)        // Ah, Al, Bh = 30720 B
#define GEMM_SMEM (3*GSTAGE_B)       // 92160 B -> 2 CTAs/SM
#define GSW       16

__device__ __forceinline__ void fill_stage(uint32_t stb,
                                           const __half* Ah0,
                                           const __half* Al0,
                                           const __half* Bh0,
                                           int K, int tid)
{
    const __half* srcs[3] = {Ah0, Al0, Bh0};
#pragma unroll
    for (int t = 0; t < 3; t++) {
        if (!srcs[t]) continue;
        uint32_t tb = stb + t * GTILE_B;
        const char* s = (const char*)srcs[t];
#pragma unroll
        for (int i = 0; i < 2; i++) {
            int id = tid + i * 256;
            int row = id >> 2, ch = id & 3;
            cp16(tb + row * (GSTRIDE * 2) + ch * 16,
                 s + (size_t)row * K * 2 + ch * 16);
        }
    }
    asm volatile("cp.async.commit_group;" ::: "memory");
}

__global__ void __launch_bounds__(256, 2)
gemm_mma_kernel(const __half* __restrict__ Ah,
                const __half* __restrict__ Al,
                const __half* __restrict__ Bh,
                float* __restrict__ C, int M, int N, int K,
                int fused,
                __half* __restrict__ Qh, __half* __restrict__ Ql,
                __half* __restrict__ Kh,
                float* __restrict__ Vb)
{
    extern __shared__ char gsm[];
    const uint32_t sbase = smem_u32(gsm);
    const int tid = threadIdx.x;
    const int wid = tid >> 5, lane = tid & 31;
    const int wm = wid & 1, wn = wid >> 1;

    // supertile rasterization
    const int Mt = M >> 7, Ntl = N >> 7;
    int mtile, ntile;
    {
        const int bid = blockIdx.x;
        const int per = GSW * Mt;
        const int fullcols = Ntl / GSW;
        if (bid < fullcols * per) {
            const int col = bid / per;
            const int r = bid % per;
            mtile = r / GSW;
            ntile = col * GSW + r % GSW;
        } else {
            const int r = bid - fullcols * per;
            const int wdt = Ntl - fullcols * GSW;
            mtile = r / wdt;
            ntile = fullcols * GSW + r % wdt;
        }
    }
    const int m0 = mtile * 128, n0 = ntile * 128;

    uint32_t a_off[4], b_off[2];
#pragma unroll
    for (int mt = 0; mt < 4; mt++)
        a_off[mt] = ((wm * 64 + mt * 16 + (lane & 15)) * GSTRIDE
                     + (lane >> 4) * 8) * 2;
#pragma unroll
    for (int np = 0; np < 2; np++)
        b_off[np] = ((wn * 32 + np * 16 + (lane & 7) + ((lane >> 4) & 1) * 8) * GSTRIDE
                     + ((lane >> 3) & 1) * 8) * 2;

    const __half* Ah0 = Ah + (size_t)m0 * K;
    const __half* Al0 = Al ? (Al + (size_t)m0 * K) : nullptr;
    const __half* Bh0 = Bh + (size_t)n0 * K;

    float acc[4][4][4];
#pragma unroll
    for (int mt = 0; mt < 4; mt++)
#pragma unroll
        for (int nt = 0; nt < 4; nt++)
#pragma unroll
            for (int r = 0; r < 4; r++) acc[mt][nt][r] = 0.f;

    const int NC = K / GKC;

#pragma unroll
    for (int c = 0; c < 3; c++)
        fill_stage(sbase + c * GSTAGE_B, Ah0 + c * GKC,
                   Al0 ? Al0 + c * GKC : nullptr,
                   Bh0 + c * GKC, K, tid);

    for (int c = 0; c < NC; c++) {
        const uint32_t stb = sbase + (c % 3) * GSTAGE_B;
        asm volatile("cp.async.wait_group %0;" :: "n"(2) : "memory");
        __syncthreads();

#pragma unroll
        for (int ks = 0; ks < 2; ks++) {
            const uint32_t ko = ks * 32;
            uint32_t ax[4][4], bx[2][4];

#pragma unroll
            for (int mt = 0; mt < 4; mt++) ldmx4(ax[mt], stb + 0 * GTILE_B + a_off[mt] + ko);
#pragma unroll
            for (int np = 0; np < 2; np++) ldmx4(bx[np], stb + 2 * GTILE_B + b_off[np] + ko);

            // term 1: Ah * B
#pragma unroll
            for (int mt = 0; mt < 4; mt++)
#pragma unroll
                for (int nt = 0; nt < 4; nt++) {
                    const int np = nt >> 1, bi = (nt & 1) * 2;
                    mma_f16(acc[mt][nt], ax[mt], bx[np][bi], bx[np][bi + 1]);
                }

            // term 2: Al * B (only when A is split)
            if (Al0) {
#pragma unroll
                for (int mt = 0; mt < 4; mt++) ldmx4(ax[mt], stb + 1 * GTILE_B + a_off[mt] + ko);
#pragma unroll
                for (int mt = 0; mt < 4; mt++)
#pragma unroll
                    for (int nt = 0; nt < 4; nt++) {
                        const int np = nt >> 1, bi = (nt & 1) * 2;
                        mma_f16(acc[mt][nt], ax[mt], bx[np][bi], bx[np][bi + 1]);
                    }
            }
        }

        __syncthreads();
        const int cn = c + 3;
        if (cn < NC)
            fill_stage(stb, Ah0 + cn * GKC,
                       Al0 ? Al0 + cn * GKC : nullptr,
                       Bh0 + cn * GKC, K, tid);
    }

    const int rr = lane >> 2, cc = (lane & 3) * 2;

    if (!fused) {
#pragma unroll
        for (int mt = 0; mt < 4; mt++) {
            const size_t mA = (size_t)(m0 + wm * 64 + mt * 16 + rr);
#pragma unroll
            for (int nt = 0; nt < 4; nt++) {
                const int n = n0 + wn * 32 + nt * 8 + cc;
                *(float2*)(C + mA * N + n) =
                    make_float2(acc[mt][nt][0], acc[mt][nt][1]);
                *(float2*)(C + (mA + 8) * N + n) =
                    make_float2(acc[mt][nt][2], acc[mt][nt][3]);
            }
        }
        return;
    }

    if (n0 >= QCOLS + KCOLS) {
        // V segment: fp32 into Vb (stride KCOLS)
#pragma unroll
        for (int mt = 0; mt < 4; mt++) {
            const size_t mA = (size_t)(m0 + wm * 64 + mt * 16 + rr);
#pragma unroll
            for (int nt = 0; nt < 4; nt++) {
                const int n = (n0 - (QCOLS + KCOLS)) + wn * 32 + nt * 8 + cc;
                *(float2*)(Vb + mA * KCOLS + n) =
                    make_float2(acc[mt][nt][0], acc[mt][nt][1]);
                *(float2*)(Vb + (mA + 8) * KCOLS + n) =
                    make_float2(acc[mt][nt][2], acc[mt][nt][3]);
            }
        }
        return;
    }

    // Q or K segment: RoPE; Q -> h/l split, K -> single fp16
    const int isQ = (n0 < QCOLS);
    const int xs = isQ ? QCOLS : KCOLS;
    const int segbase = isQ ? 0 : QCOLS;

#pragma unroll
    for (int mt = 0; mt < 4; mt++) {
        const int mA = m0 + wm * 64 + mt * 16 + rr;
#pragma unroll
        for (int nt = 0; nt < 4; nt++) {
            const int colp = (n0 - segbase) + wn * 32 + nt * 8 + cc; // even
            const int head = colp >> 8;
            const int i    = (colp & 255) >> 1;
            const int ca   = head * 256 + i;
            const int cb   = ca + 128;
#pragma unroll
            for (int rh = 0; rh < 2; rh++) {
                const int m   = mA + rh * 8;
                const int pos = m & (SEQ - 1);
                const float co = g_cos[pos * 128 + i];
                const float si = g_sin[pos * 128 + i];
                const float x1 = acc[mt][nt][rh * 2 + 0];
                const float x2 = acc[mt][nt][rh * 2 + 1];
                const float y1 = x1 * co - x2 * si;
                const float y2 = x2 * co + x1 * si;
                const size_t rb = (size_t)m * xs;
                if (isQ) {
                    const __half h1 = __float2half(y1);
                    const __half h2 = __float2half(y2);
                    Qh[rb + ca] = h1;
                    Qh[rb + cb] = h2;
                    Ql[rb + ca] = __float2half(y1 - __half2float(h1));
                    Ql[rb + cb] = __float2half(y2 - __half2float(h2));
                } else {
                    Kh[rb + ca] = __float2half(y1);
                    Kh[rb + cb] = __float2half(y2);
                }
            }
        }
    }
}

// ---------------------------------------------------------------------------
// Tensor-core flash attention: S = (Qh+Ql)K^T (2 terms), O += P V (P single),
// no-max softmax (|logit| <= 50), FMA-pipe exp/rcp. Output: single fp16 C.
// ---------------------------------------------------------------------------
#define DST 264   // Q/K smem row stride (fp16)
#define VST 72
#define PST 72
#define oQh 0
#define oQl 33792
#define oKh 67584
#define oVh 101376
#define oPh 138240
#define oLrow 147456
#define ATTN_SMEM (147456 + 256)

__global__ void __launch_bounds__(256, 1)
attn_tc_kernel(const __half* __restrict__ Qh, const __half* __restrict__ Ql,
               const __half* __restrict__ Kh,
               const __half* __restrict__ Vth,
               __half* __restrict__ Ch)
{
    extern __shared__ char smraw[];
    const uint32_t sb = smem_u32(smraw);
    float* lrow = (float*)(smraw + oLrow);

    const int tid = threadIdx.x;
    const int wid = tid >> 5, lane = tid & 31;
    const int wq = wid & 3, wh = wid >> 2;
    const int b  = blockIdx.y >> 4;
    const int h  = blockIdx.y & 15;
    const int kvh = h >> 1;
    const int q0 = blockIdx.x * 64;

    const char* gQh = (const char*)(Qh + ((size_t)(b * SEQ + q0)) * QCOLS + h * HDIM);
    const char* gQl = (const char*)(Ql + ((size_t)(b * SEQ + q0)) * QCOLS + h * HDIM);
    const char* gKh = (const char*)(Kh + ((size_t)(b * SEQ)) * KCOLS + kvh * HDIM);
    const char* gVh = (const char*)(Vth + ((size_t)(b * KCOLS + kvh * HDIM)) * SEQ);

    if (tid < 64) lrow[tid] = 0.f;

    int klo = q0 - WINDOW;       if (klo < 0) klo = 0;
    int khi = q0 + 64 + WINDOW;  if (khi > SEQ) khi = SEQ;
    const int kt0 = klo >> 6;
    const int ntiles = (khi >> 6) - kt0;

#pragma unroll
    for (int i = 0; i < 8; i++) {
        int id = tid + i * 256;
        int row = id >> 5, ch = id & 31;
        cp16(sb + oQh + row * (DST * 2) + ch * 16, gQh + (size_t)row * (QCOLS * 2) + ch * 16);
        cp16(sb + oQl + row * (DST * 2) + ch * 16, gQl + (size_t)row * (QCOLS * 2) + ch * 16);
    }
    {
        int kb = kt0 * 64;
#pragma unroll
        for (int i = 0; i < 8; i++) {
            int id = tid + i * 256;
            int row = id >> 5, ch = id & 31;
            cp16(sb + oKh + row * (DST * 2) + ch * 16, gKh + (size_t)(kb + row) * (KCOLS * 2) + ch * 16);
        }
        asm volatile("cp.async.commit_group;" ::: "memory");
#pragma unroll
        for (int i = 0; i < 8; i++) {
            int id = tid + i * 256;
            int row = id >> 3, ch = id & 7;
            cp16(sb + oVh + row * (VST * 2) + ch * 16, gVh + (size_t)row * (SEQ * 2) + kb * 2 + ch * 16);
        }
        asm volatile("cp.async.commit_group;" ::: "memory");
    }
    asm volatile("cp.async.wait_group %0;" :: "n"(1) : "memory");
    __syncthreads();

    const uint32_t a_off = ((wq * 16 + (lane & 15)) * DST + (lane >> 4) * 8) * 2;
    uint32_t bs_off[2];
#pragma unroll
    for (int np = 0; np < 2; np++)
        bs_off[np] = ((wh * 32 + np * 16 + (lane & 7) + ((lane >> 4) & 1) * 8) * DST
                      + ((lane >> 3) & 1) * 8) * 2;
    const uint32_t ap_off = ((wq * 16 + (lane & 15)) * PST + (lane >> 4) * 8) * 2;
    uint32_t bv_off[8];
#pragma unroll
    for (int np = 0; np < 8; np++)
        bv_off[np] = ((wh * 128 + np * 16 + (lane & 7) + ((lane >> 4) & 1) * 8) * VST
                      + ((lane >> 3) & 1) * 8) * 2;

    float oacc[16][4];
#pragma unroll
    for (int nt = 0; nt < 16; nt++)
#pragma unroll
        for (int r = 0; r < 4; r++) oacc[nt][r] = 0.f;

    const int r0 = wq * 16 + (lane >> 2), r1 = r0 + 8;
    const int qg0 = q0 + r0, qg1 = q0 + r1;

    for (int t = 0; t < ntiles; t++) {
        const int kbase = (kt0 + t) * 64;

        // ---- S = (Qh+Ql) K^T ----
        float sacc[4][4];
#pragma unroll
        for (int nt = 0; nt < 4; nt++)
#pragma unroll
            for (int r = 0; r < 4; r++) sacc[nt][r] = 0.f;

#pragma unroll 4
        for (int ks = 0; ks < 16; ks++) {
            const uint32_t ko = ks * 32;
            uint32_t qhf[4], qlf[4], khf[2][4];
            ldmx4(qhf, sb + oQh + a_off + ko);
            ldmx4(qlf, sb + oQl + a_off + ko);
#pragma unroll
            for (int np = 0; np < 2; np++)
                ldmx4(khf[np], sb + oKh + bs_off[np] + ko);
#pragma unroll
            for (int nt = 0; nt < 4; nt++) {
                const int np = nt >> 1, bi = (nt & 1) * 2;
                mma_f16(sacc[nt], qhf, khf[np][bi], khf[np][bi + 1]);
                mma_f16(sacc[nt], qlf, khf[np][bi], khf[np][bi + 1]);
            }
        }

        // ---- soft-cap + window mask + exp, write P (single fp16) ----
        float psum0 = 0.f, psum1 = 0.f;
#pragma unroll
        for (int nt = 0; nt < 4; nt++) {
            const int cl = wh * 32 + nt * 8 + (lane & 3) * 2;
            const int cg = kbase + cl;
            float p[4];
#pragma unroll
            for (int e = 0; e < 4; e++) {
                const int qg = (e < 2) ? qg0 : qg1;
                const int kg = cg + (e & 1);
                int dlt = qg - kg; if (dlt < 0) dlt = -dlt;
                if (dlt <= WINDOW) {
                    float E = fexp(sacc[nt][e] * 0.0025f);
                    float l = fmaf(-100.f, frcp(E + 1.f), 50.f);
                    p[e] = fexp(l);
                } else p[e] = 0.f;
            }
            psum0 += p[0] + p[1];
            psum1 += p[2] + p[3];
            *(__half2*)(smraw + oPh + (r0 * PST + cl) * 2) =
                __halves2half2(__float2half(p[0]), __float2half(p[1]));
            *(__half2*)(smraw + oPh + (r1 * PST + cl) * 2) =
                __halves2half2(__float2half(p[2]), __float2half(p[3]));
        }
        psum0 += __shfl_xor_sync(0xffffffffu, psum0, 1);
        psum0 += __shfl_xor_sync(0xffffffffu, psum0, 2);
        psum1 += __shfl_xor_sync(0xffffffffu, psum1, 1);
        psum1 += __shfl_xor_sync(0xffffffffu, psum1, 2);
        if ((lane & 3) == 0) {
            atomicAdd(&lrow[r0], psum0);
            atomicAdd(&lrow[r1], psum1);
        }

        asm volatile("cp.async.wait_group %0;" :: "n"(0) : "memory");
        __syncthreads();

        if (t + 1 < ntiles) {                 // prefetch K(t+1)
            int kb = kbase + 64;
#pragma unroll
            for (int i = 0; i < 8; i++) {
                int id = tid + i * 256;
                int row = id >> 5, ch = id & 31;
                cp16(sb + oKh + row * (DST * 2) + ch * 16, gKh + (size_t)(kb + row) * (KCOLS * 2) + ch * 16);
            }
            asm volatile("cp.async.commit_group;" ::: "memory");
        }

        // ---- O += P V (single-term) ----
#pragma unroll
        for (int kp = 0; kp < 4; kp++) {
            const uint32_t ko = kp * 32;
            uint32_t pah[4];
            ldmx4(pah, sb + oPh + ap_off + ko);
#pragma unroll
            for (int np = 0; np < 8; np++) {
                uint32_t vbh[4];
                ldmx4(vbh, sb + oVh + bv_off[np] + ko);
#pragma unroll
                for (int i = 0; i < 2; i++) {
                    const int nt = np * 2 + i, bi = i * 2;
                    mma_f16(oacc[nt], pah, vbh[bi], vbh[bi + 1]);
                }
            }
        }
        __syncthreads();

        if (t + 1 < ntiles) {                 // prefetch V(t+1)
            int kb = kbase + 64;
#pragma unroll
            for (int i = 0; i < 8; i++) {
                int id = tid + i * 256;
                int row = id >> 3, ch = id & 7;
                cp16(sb + oVh + row * (VST * 2) + ch * 16, gVh + (size_t)row * (SEQ * 2) + kb * 2 + ch * 16);
            }
            asm volatile("cp.async.commit_group;" ::: "memory");
            asm volatile("cp.async.wait_group %0;" :: "n"(1) : "memory");
        }
        __syncthreads();
    }

    // ---- normalize, write context (single fp16) ----
    const float inv0 = 1.0f / lrow[r0];
    const float inv1 = 1.0f / lrow[r1];
    const size_t row0 = (size_t)(b * SEQ + q0 + r0) * QCOLS;
    const size_t row1 = (size_t)(b * SEQ + q0 + r1) * QCOLS;
#pragma unroll
    for (int nt = 0; nt < 16; nt++) {
        const int col = h * HDIM + wh * 128 + nt * 8 + (lane & 3) * 2;
        *(__half2*)(Ch + row0 + col) =
            __halves2half2(__float2half(oacc[nt][0] * inv0),
                           __float2half(oacc[nt][1] * inv0));
        *(__half2*)(Ch + row1 + col) =
            __halves2half2(__float2half(oacc[nt][2] * inv1),
                           __float2half(oacc[nt][3] * inv1));
    }
}

// ---------------------------------------------------------------------------
// launch
// ---------------------------------------------------------------------------
extern "C" void kernel_launch(void* const* d_in, const int* in_sizes, int n_in,
                              void* d_out, int out_size)
{
    const float* hid = (const float*)d_in[0];
    const float* Wq  = (const float*)d_in[1];
    const float* Wk  = (const float*)d_in[2];
    const float* Wv  = (const float*)d_in[3];
    const float* Wo  = (const float*)d_in[4];
    float* out = (float*)d_out;

    float *Vb;
    cudaGetSymbolAddress((void**)&Vb, g_V);

    __half *Hh, *Hl, *WpH, *WotH, *Ch, *Qh, *Ql, *Kh, *VtH;
    cudaGetSymbolAddress((void**)&Hh,   g_Hh);
    cudaGetSymbolAddress((void**)&Hl,   g_Hl);
    cudaGetSymbolAddress((void**)&WpH,  g_WpH);
    cudaGetSymbolAddress((void**)&WotH, g_WotH);
    cudaGetSymbolAddress((void**)&Ch,   g_Ch);
    cudaGetSymbolAddress((void**)&Qh,   g_Qh);
    cudaGetSymbolAddress((void**)&Ql,   g_Ql);
    cudaGetSymbolAddress((void**)&Kh,   g_Kh);
    cudaGetSymbolAddress((void**)&VtH,  g_VtH);

    cudaFuncSetAttribute(gemm_mma_kernel, cudaFuncAttributeMaxDynamicSharedMemorySize,
                         GEMM_SMEM);
    cudaFuncSetAttribute(attn_tc_kernel, cudaFuncAttributeMaxDynamicSharedMemorySize,
                         ATTN_SMEM);

    rope_tables_kernel<<<(SEQ * 128 + 255) / 256, 256>>>();

    // preprocessing (Q/K cols permuted for RoPE-fused epilogue)
    split_kernel<<<(MROWS * EMBED / 4 + 255) / 256, 256>>>(hid, Hh, Hl, MROWS * EMBED / 4);
    tsplit_kernel<<<dim3(QCOLS / 32, EMBED / 32), dim3(32, 8)>>>(Wq, WpH, EMBED, QCOLS, 1, 0);
    tsplit_kernel<<<dim3(KCOLS / 32, EMBED / 32), dim3(32, 8)>>>(Wk, WpH, EMBED, KCOLS, 1, QCOLS);
    tsplit_kernel<<<dim3(KCOLS / 32, EMBED / 32), dim3(32, 8)>>>(Wv, WpH, EMBED, KCOLS, 0, QCOLS + KCOLS);
    tsplit_kernel<<<dim3(EMBED / 32, QCOLS / 32), dim3(32, 8)>>>(Wo, WotH, QCOLS, EMBED, 0, 0);

    // fused QKV projection (A split: Hh+Hl)
    gemm_mma_kernel<<<dim3((NPACK / 128) * (MROWS / 128)), 256, GEMM_SMEM>>>(
        Hh, Hl, WpH, nullptr, MROWS, NPACK, EMBED,
        1, Qh, Ql, Kh, Vb);

    // V transpose
    vtsplit_kernel<<<dim3(SEQ / 32, KCOLS / 32, BATCH), dim3(32, 8)>>>(Vb, VtH);

    // attention -> Ch single fp16
    attn_tc_kernel<<<dim3(SEQ / 64, BATCH * NH), 256, ATTN_SMEM>>>(
        Qh, Ql, Kh, VtH, Ch);

    // output projection (A single: Ch) straight into d_out
    gemm_mma_kernel<<<dim3((EMBED / 128) * (MROWS / 128)), 256, GEMM_SMEM>>>(
        Ch, nullptr, WotH, out, MROWS, EMBED, QCOLS,
        0, nullptr, nullptr, nullptr, nullptr);
}

// round 16
// speedup vs baseline: 1.7677x; 1.0627x over previous
#include <cuda_runtime.h>
#include <cuda_fp16.h>
#include <math.h>
#include <stdint.h>

// ---------------------------------------------------------------------------
// Problem constants
// ---------------------------------------------------------------------------
#define BATCH   2
#define SEQ     2048
#define EMBED   3584
#define NH      16
#define NKV     8
#define HDIM    256
#define MROWS   (BATCH*SEQ)          // 4096
#define QCOLS   (NH*HDIM)            // 4096
#define KCOLS   (NKV*HDIM)           // 2048
#define NPACK   (QCOLS + 2*KCOLS)    // 8192 packed QKV columns
#define WINDOW  1024

// ---------------------------------------------------------------------------
// Static device scratch (no cudaMalloc allowed)
// ---------------------------------------------------------------------------
__device__ float g_V  [(size_t)MROWS*KCOLS];
__device__ float g_cos[SEQ*(HDIM/2)];
__device__ float g_sin[SEQ*(HDIM/2)];

// fp16 operands
__device__ __half g_Hh [(size_t)MROWS*EMBED];
__device__ __half g_Hl [(size_t)MROWS*EMBED];
__device__ __half g_WpH[(size_t)NPACK*EMBED];    // packed Wq|Wk|Wv, transposed
__device__ __half g_WotH[(size_t)EMBED*QCOLS];   // Wo transposed
__device__ __half g_Ch [(size_t)MROWS*QCOLS];    // attention output, single fp16

// attention operands
__device__ __half g_Qh [(size_t)MROWS*QCOLS];
__device__ __half g_Ql [(size_t)MROWS*QCOLS];
__device__ __half g_Kh [(size_t)MROWS*KCOLS];    // single fp16 (B side)
__device__ __half g_VtH[(size_t)MROWS*KCOLS];    // per-batch transposed [KCOLS][SEQ]

// ---------------------------------------------------------------------------
// PTX helpers (sm_100-safe)
// ---------------------------------------------------------------------------
__device__ __forceinline__ uint32_t smem_u32(const void* p) {
    uint32_t a;
    asm("{ .reg .u64 t; cvta.to.shared.u64 t, %1; cvt.u32.u64 %0, t; }" : "=r"(a) : "l"(p));
    return a;
}
__device__ __forceinline__ void cp16(uint32_t dst, const void* src) {
    asm volatile("cp.async.cg.shared.global [%0], [%1], 16;" :: "r"(dst), "l"(src) : "memory");
}
__device__ __forceinline__ void ldmx4(uint32_t* r, uint32_t addr) {
    asm volatile("ldmatrix.sync.aligned.m8n8.x4.shared.b16 {%0,%1,%2,%3}, [%4];"
                 : "=r"(r[0]), "=r"(r[1]), "=r"(r[2]), "=r"(r[3]) : "r"(addr));
}
__device__ __forceinline__ void mma_f16(float* c, const uint32_t* a,
                                        uint32_t b0, uint32_t b1) {
    asm volatile(
        "mma.sync.aligned.m16n8k16.row.col.f32.f16.f16.f32 "
        "{%0,%1,%2,%3}, {%4,%5,%6,%7}, {%8,%9}, {%0,%1,%2,%3};"
        : "+f"(c[0]), "+f"(c[1]), "+f"(c[2]), "+f"(c[3])
        : "r"(a[0]), "r"(a[1]), "r"(a[2]), "r"(a[3]), "r"(b0), "r"(b1));
}

// FMA-pipe exp (no MUFU): e^x for |x| <= ~85, rel err ~1.5e-7
__device__ __forceinline__ float fexp(float x) {
    float y  = x * 1.4426950408889634f;
    float fm = y + 12582912.0f;
    float nf = fm - 12582912.0f;
    float f  = y - nf;
    int   sc = ((__float_as_int(fm) - 0x4B400000) + 127) << 23;
    float t  = f * 0.6931471805599453f;
    float p  = 1.0f + t*(1.0f + t*(0.5f + t*(0.16666667f +
               t*(0.041666667f + t*(0.008333334f + t*0.0013888889f)))));
    return p * __int_as_float(sc);
}
// FMA-pipe reciprocal (bit-hack + 3 Newton)
__device__ __forceinline__ float frcp(float d) {
    float r = __int_as_float(0x7EF311C3 - __float_as_int(d));
    r = r * (2.0f - d * r);
    r = r * (2.0f - d * r);
    r = r * (2.0f - d * r);
    return r;
}

// ---------------------------------------------------------------------------
// fp32 -> fp16 hi/lo split (vectorized)
// ---------------------------------------------------------------------------
__global__ void split_kernel(const float* __restrict__ in,
                             __half* __restrict__ hi,
                             __half* __restrict__ lo, int n4)
{
    int i = blockIdx.x * 256 + threadIdx.x;
    if (i >= n4) return;
    float4 v = ((const float4*)in)[i];
    __half h0 = __float2half(v.x);
    __half h1 = __float2half(v.y);
    __half h2 = __float2half(v.z);
    __half h3 = __float2half(v.w);
    __half l0 = __float2half(v.x - __half2float(h0));
    __half l1 = __float2half(v.y - __half2float(h1));
    __half l2 = __float2half(v.z - __half2float(h2));
    __half l3 = __float2half(v.w - __half2float(h3));
    ((__half2*)hi)[2*i]   = __halves2half2(h0, h1);
    ((__half2*)hi)[2*i+1] = __halves2half2(h2, h3);
    ((__half2*)lo)[2*i]   = __halves2half2(l0, l1);
    ((__half2*)lo)[2*i+1] = __halves2half2(l2, l3);
}

// ---------------------------------------------------------------------------
// Transpose (+optional RoPE-pair perm): W [K,N] fp32 -> Th [rowoff+perm(n)][K] fp16
// ---------------------------------------------------------------------------
__global__ void tsplit_kernel(const float* __restrict__ W,
                              __half* __restrict__ Th, int K, int N,
                              int perm, int rowoff)
{
    __shared__ float t[32][33];
    int n0 = blockIdx.x * 32, k0 = blockIdx.y * 32;
    int tx = threadIdx.x, ty = threadIdx.y;
#pragma unroll
    for (int i = 0; i < 32; i += 8)
        t[ty + i][tx] = W[(size_t)(k0 + ty + i) * N + n0 + tx];
    __syncthreads();
#pragma unroll
    for (int i = 0; i < 32; i += 8) {
        float v = t[tx][ty + i];
        int n = n0 + ty + i;
        int nb = n & 255;
        int np = perm ? ((n & ~255) + ((nb < 128) ? (nb << 1) : (((nb - 128) << 1) | 1)))
                      : n;
        Th[(size_t)(rowoff + np) * K + k0 + tx] = __float2half(v);
    }
}

// ---------------------------------------------------------------------------
// V transpose per batch: g_V [b*SEQ+s][KCOLS] -> Vt [b][KCOLS][SEQ] fp16
// ---------------------------------------------------------------------------
__global__ void vtsplit_kernel(const float* __restrict__ V,
                               __half* __restrict__ Th)
{
    __shared__ float t[32][33];
    int s0 = blockIdx.x * 32, c0 = blockIdx.y * 32, b = blockIdx.z;
    int tx = threadIdx.x, ty = threadIdx.y;
#pragma unroll
    for (int i = 0; i < 32; i += 8)
        t[ty + i][tx] = V[((size_t)b * SEQ + s0 + ty + i) * KCOLS + c0 + tx];
    __syncthreads();
#pragma unroll
    for (int i = 0; i < 32; i += 8) {
        float v = t[tx][ty + i];
        size_t o = ((size_t)b * KCOLS + c0 + ty + i) * SEQ + s0 + tx;
        Th[o] = __float2half(v);
    }
}

// ---------------------------------------------------------------------------
// RoPE tables (double precision)
// ---------------------------------------------------------------------------
__global__ void rope_tables_kernel()
{
    int idx = blockIdx.x * 256 + threadIdx.x;
    if (idx >= SEQ * (HDIM / 2)) return;
    int i = idx & 127;
    int pos = idx >> 7;
    double invf = pow(10000.0, -(double)(2 * i) / (double)HDIM);
    double ang = (double)pos * invf;
    g_cos[idx] = (float)cos(ang);
    g_sin[idx] = (float)sin(ang);
}

// ---------------------------------------------------------------------------
// mma.sync fp16 GEMM: C = (Ah[+Al])[M,K] @ Bh[N,K]^T, 3-stage pipeline,
// 2 CTAs/SM, supertile rasterization. Al==nullptr -> single-term A.
// mode 0: plain fp32 C. mode 1: fused QKV (RoPE epilogue Q->h/l, K->single,
// V segment -> Vb fp32, computed single-term: Al skipped for V columns).
// ---------------------------------------------------------------------------
#define GKC       32
#define GSTRIDE   40
#define GTILE_B   (128*GSTRIDE*2)    // 10240 B per tile
#define GSTAGE_B  (3*GTILE_B)        // Ah, Al, Bh = 30720 B
#define GEMM_SMEM (3*GSTAGE_B)       // 92160 B -> 2 CTAs/SM
#define GSW       16

__device__ __forceinline__ void fill_stage(uint32_t stb,
                                           const __half* Ah0,
                                           const __half* Al0,
                                           const __half* Bh0,
                                           int K, int tid)
{
    const __half* srcs[3] = {Ah0, Al0, Bh0};
#pragma unroll
    for (int t = 0; t < 3; t++) {
        if (!srcs[t]) continue;
        uint32_t tb = stb + t * GTILE_B;
        const char* s = (const char*)srcs[t];
#pragma unroll
        for (int i = 0; i < 2; i++) {
            int id = tid + i * 256;
            int row = id >> 2, ch = id & 3;
            cp16(tb + row * (GSTRIDE * 2) + ch * 16,
                 s + (size_t)row * K * 2 + ch * 16);
        }
    }
    asm volatile("cp.async.commit_group;" ::: "memory");
}

__global__ void __launch_bounds__(256, 2)
gemm_mma_kernel(const __half* __restrict__ Ah,
                const __half* __restrict__ Al,
                const __half* __restrict__ Bh,
                float* __restrict__ C, int M, int N, int K,
                int fused,
                __half* __restrict__ Qh, __half* __restrict__ Ql,
                __half* __restrict__ Kh,
                float* __restrict__ Vb)
{
    extern __shared__ char gsm[];
    const uint32_t sbase = smem_u32(gsm);
    const int tid = threadIdx.x;
    const int wid = tid >> 5, lane = tid & 31;
    const int wm = wid & 1, wn = wid >> 1;

    // supertile rasterization
    const int Mt = M >> 7, Ntl = N >> 7;
    int mtile, ntile;
    {
        const int bid = blockIdx.x;
        const int per = GSW * Mt;
        const int fullcols = Ntl / GSW;
        if (bid < fullcols * per) {
            const int col = bid / per;
            const int r = bid % per;
            mtile = r / GSW;
            ntile = col * GSW + r % GSW;
        } else {
            const int r = bid - fullcols * per;
            const int wdt = Ntl - fullcols * GSW;
            mtile = r / wdt;
            ntile = fullcols * GSW + r % wdt;
        }
    }
    const int m0 = mtile * 128, n0 = ntile * 128;

    // V-segment columns are computed single-term (Al dropped): their error
    // path (V -> PV -> O) has unit gain, unlike Q/K which feed logits.
    const bool useAl = (Al != nullptr) && !(fused && n0 >= QCOLS + KCOLS);

    uint32_t a_off[4], b_off[2];
#pragma unroll
    for (int mt = 0; mt < 4; mt++)
        a_off[mt] = ((wm * 64 + mt * 16 + (lane & 15)) * GSTRIDE
                     + (lane >> 4) * 8) * 2;
#pragma unroll
    for (int np = 0; np < 2; np++)
        b_off[np] = ((wn * 32 + np * 16 + (lane & 7) + ((lane >> 4) & 1) * 8) * GSTRIDE
                     + ((lane >> 3) & 1) * 8) * 2;

    const __half* Ah0 = Ah + (size_t)m0 * K;
    const __half* Al0 = useAl ? (Al + (size_t)m0 * K) : nullptr;
    const __half* Bh0 = Bh + (size_t)n0 * K;

    float acc[4][4][4];
#pragma unroll
    for (int mt = 0; mt < 4; mt++)
#pragma unroll
        for (int nt = 0; nt < 4; nt++)
#pragma unroll
            for (int r = 0; r < 4; r++) acc[mt][nt][r] = 0.f;

    const int NC = K / GKC;

#pragma unroll
    for (int c = 0; c < 3; c++)
        fill_stage(sbase + c * GSTAGE_B, Ah0 + c * GKC,
                   Al0 ? Al0 + c * GKC : nullptr,
                   Bh0 + c * GKC, K, tid);

    for (int c = 0; c < NC; c++) {
        const uint32_t stb = sbase + (c % 3) * GSTAGE_B;
        asm volatile("cp.async.wait_group %0;" :: "n"(2) : "memory");
        __syncthreads();

#pragma unroll
        for (int ks = 0; ks < 2; ks++) {
            const uint32_t ko = ks * 32;
            uint32_t ax[4][4], bx[2][4];

#pragma unroll
            for (int mt = 0; mt < 4; mt++) ldmx4(ax[mt], stb + 0 * GTILE_B + a_off[mt] + ko);
#pragma unroll
            for (int np = 0; np < 2; np++) ldmx4(bx[np], stb + 2 * GTILE_B + b_off[np] + ko);

            // term 1: Ah * B
#pragma unroll
            for (int mt = 0; mt < 4; mt++)
#pragma unroll
                for (int nt = 0; nt < 4; nt++) {
                    const int np = nt >> 1, bi = (nt & 1) * 2;
                    mma_f16(acc[mt][nt], ax[mt], bx[np][bi], bx[np][bi + 1]);
                }

            // term 2: Al * B (only when A is split)
            if (Al0) {
#pragma unroll
                for (int mt = 0; mt < 4; mt++) ldmx4(ax[mt], stb + 1 * GTILE_B + a_off[mt] + ko);
#pragma unroll
                for (int mt = 0; mt < 4; mt++)
#pragma unroll
                    for (int nt = 0; nt < 4; nt++) {
                        const int np = nt >> 1, bi = (nt & 1) * 2;
                        mma_f16(acc[mt][nt], ax[mt], bx[np][bi], bx[np][bi + 1]);
                    }
            }
        }

        __syncthreads();
        const int cn = c + 3;
        if (cn < NC)
            fill_stage(stb, Ah0 + cn * GKC,
                       Al0 ? Al0 + cn * GKC : nullptr,
                       Bh0 + cn * GKC, K, tid);
    }

    const int rr = lane >> 2, cc = (lane & 3) * 2;

    if (!fused) {
#pragma unroll
        for (int mt = 0; mt < 4; mt++) {
            const size_t mA = (size_t)(m0 + wm * 64 + mt * 16 + rr);
#pragma unroll
            for (int nt = 0; nt < 4; nt++) {
                const int n = n0 + wn * 32 + nt * 8 + cc;
                *(float2*)(C + mA * N + n) =
                    make_float2(acc[mt][nt][0], acc[mt][nt][1]);
                *(float2*)(C + (mA + 8) * N + n) =
                    make_float2(acc[mt][nt][2], acc[mt][nt][3]);
            }
        }
        return;
    }

    if (n0 >= QCOLS + KCOLS) {
        // V segment: fp32 into Vb (stride KCOLS)
#pragma unroll
        for (int mt = 0; mt < 4; mt++) {
            const size_t mA = (size_t)(m0 + wm * 64 + mt * 16 + rr);
#pragma unroll
            for (int nt = 0; nt < 4; nt++) {
                const int n = (n0 - (QCOLS + KCOLS)) + wn * 32 + nt * 8 + cc;
                *(float2*)(Vb + mA * KCOLS + n) =
                    make_float2(acc[mt][nt][0], acc[mt][nt][1]);
                *(float2*)(Vb + (mA + 8) * KCOLS + n) =
                    make_float2(acc[mt][nt][2], acc[mt][nt][3]);
            }
        }
        return;
    }

    // Q or K segment: RoPE; Q -> h/l split, K -> single fp16
    const int isQ = (n0 < QCOLS);
    const int xs = isQ ? QCOLS : KCOLS;
    const int segbase = isQ ? 0 : QCOLS;

#pragma unroll
    for (int mt = 0; mt < 4; mt++) {
        const int mA = m0 + wm * 64 + mt * 16 + rr;
#pragma unroll
        for (int nt = 0; nt < 4; nt++) {
            const int colp = (n0 - segbase) + wn * 32 + nt * 8 + cc; // even
            const int head = colp >> 8;
            const int i    = (colp & 255) >> 1;
            const int ca   = head * 256 + i;
            const int cb   = ca + 128;
#pragma unroll
            for (int rh = 0; rh < 2; rh++) {
                const int m   = mA + rh * 8;
                const int pos = m & (SEQ - 1);
                const float co = g_cos[pos * 128 + i];
                const float si = g_sin[pos * 128 + i];
                const float x1 = acc[mt][nt][rh * 2 + 0];
                const float x2 = acc[mt][nt][rh * 2 + 1];
                const float y1 = x1 * co - x2 * si;
                const float y2 = x2 * co + x1 * si;
                const size_t rb = (size_t)m * xs;
                if (isQ) {
                    const __half h1 = __float2half(y1);
                    const __half h2 = __float2half(y2);
                    Qh[rb + ca] = h1;
                    Qh[rb + cb] = h2;
                    Ql[rb + ca] = __float2half(y1 - __half2float(h1));
                    Ql[rb + cb] = __float2half(y2 - __half2float(h2));
                } else {
                    Kh[rb + ca] = __float2half(y1);
                    Kh[rb + cb] = __float2half(y2);
                }
            }
        }
    }
}

// ---------------------------------------------------------------------------
// Tensor-core flash attention: S = (Qh+Ql)K^T (2 terms), O += P V (P single),
// no-max softmax (|logit| <= 50), FMA-pipe exp/rcp. Output: single fp16 C.
// ---------------------------------------------------------------------------
#define DST 264   // Q/K smem row stride (fp16)
#define VST 72
#define PST 72
#define oQh 0
#define oQl 33792
#define oKh 67584
#define oVh 101376
#define oPh 138240
#define oLrow 147456
#define ATTN_SMEM (147456 + 256)

__global__ void __launch_bounds__(256, 1)
attn_tc_kernel(const __half* __restrict__ Qh, const __half* __restrict__ Ql,
               const __half* __restrict__ Kh,
               const __half* __restrict__ Vth,
               __half* __restrict__ Ch)
{
    extern __shared__ char smraw[];
    const uint32_t sb = smem_u32(smraw);
    float* lrow = (float*)(smraw + oLrow);

    const int tid = threadIdx.x;
    const int wid = tid >> 5, lane = tid & 31;
    const int wq = wid & 3, wh = wid >> 2;
    const int b  = blockIdx.y >> 4;
    const int h  = blockIdx.y & 15;
    const int kvh = h >> 1;
    const int q0 = blockIdx.x * 64;

    const char* gQh = (const char*)(Qh + ((size_t)(b * SEQ + q0)) * QCOLS + h * HDIM);
    const char* gQl = (const char*)(Ql + ((size_t)(b * SEQ + q0)) * QCOLS + h * HDIM);
    const char* gKh = (const char*)(Kh + ((size_t)(b * SEQ)) * KCOLS + kvh * HDIM);
    const char* gVh = (const char*)(Vth + ((size_t)(b * KCOLS + kvh * HDIM)) * SEQ);

    if (tid < 64) lrow[tid] = 0.f;

    int klo = q0 - WINDOW;       if (klo < 0) klo = 0;
    int khi = q0 + 64 + WINDOW;  if (khi > SEQ) khi = SEQ;
    const int kt0 = klo >> 6;
    const int ntiles = (khi >> 6) - kt0;

#pragma unroll
    for (int i = 0; i < 8; i++) {
        int id = tid + i * 256;
        int row = id >> 5, ch = id & 31;
        cp16(sb + oQh + row * (DST * 2) + ch * 16, gQh + (size_t)row * (QCOLS * 2) + ch * 16);
        cp16(sb + oQl + row * (DST * 2) + ch * 16, gQl + (size_t)row * (QCOLS * 2) + ch * 16);
    }
    {
        int kb = kt0 * 64;
#pragma unroll
        for (int i = 0; i < 8; i++) {
            int id = tid + i * 256;
            int row = id >> 5, ch = id & 31;
            cp16(sb + oKh + row * (DST * 2) + ch * 16, gKh + (size_t)(kb + row) * (KCOLS * 2) + ch * 16);
        }
        asm volatile("cp.async.commit_group;" ::: "memory");
#pragma unroll
        for (int i = 0; i < 8; i++) {
            int id = tid + i * 256;
            int row = id >> 3, ch = id & 7;
            cp16(sb + oVh + row * (VST * 2) + ch * 16, gVh + (size_t)row * (SEQ * 2) + kb * 2 + ch * 16);
        }
        asm volatile("cp.async.commit_group;" ::: "memory");
    }
    asm volatile("cp.async.wait_group %0;" :: "n"(1) : "memory");
    __syncthreads();

    const uint32_t a_off = ((wq * 16 + (lane & 15)) * DST + (lane >> 4) * 8) * 2;
    uint32_t bs_off[2];
#pragma unroll
    for (int np = 0; np < 2; np++)
        bs_off[np] = ((wh * 32 + np * 16 + (lane & 7) + ((lane >> 4) & 1) * 8) * DST
                      + ((lane >> 3) & 1) * 8) * 2;
    const uint32_t ap_off = ((wq * 16 + (lane & 15)) * PST + (lane >> 4) * 8) * 2;
    uint32_t bv_off[8];
#pragma unroll
    for (int np = 0; np < 8; np++)
        bv_off[np] = ((wh * 128 + np * 16 + (lane & 7) + ((lane >> 4) & 1) * 8) * VST
                      + ((lane >> 3) & 1) * 8) * 2;

    float oacc[16][4];
#pragma unroll
    for (int nt = 0; nt < 16; nt++)
#pragma unroll
        for (int r = 0; r < 4; r++) oacc[nt][r] = 0.f;

    const int r0 = wq * 16 + (lane >> 2), r1 = r0 + 8;
    const int qg0 = q0 + r0, qg1 = q0 + r1;

    for (int t = 0; t < ntiles; t++) {
        const int kbase = (kt0 + t) * 64;

        // ---- S = (Qh+Ql) K^T ----
        float sacc[4][4];
#pragma unroll
        for (int nt = 0; nt < 4; nt++)
#pragma unroll
            for (int r = 0; r < 4; r++) sacc[nt][r] = 0.f;

#pragma unroll 4
        for (int ks = 0; ks < 16; ks++) {
            const uint32_t ko = ks * 32;
            uint32_t qhf[4], qlf[4], khf[2][4];
            ldmx4(qhf, sb + oQh + a_off + ko);
            ldmx4(qlf, sb + oQl + a_off + ko);
#pragma unroll
            for (int np = 0; np < 2; np++)
                ldmx4(khf[np], sb + oKh + bs_off[np] + ko);
#pragma unroll
            for (int nt = 0; nt < 4; nt++) {
                const int np = nt >> 1, bi = (nt & 1) * 2;
                mma_f16(sacc[nt], qhf, khf[np][bi], khf[np][bi + 1]);
                mma_f16(sacc[nt], qlf, khf[np][bi], khf[np][bi + 1]);
            }
        }

        // ---- soft-cap + window mask + exp, write P (single fp16) ----
        float psum0 = 0.f, psum1 = 0.f;
#pragma unroll
        for (int nt = 0; nt < 4; nt++) {
            const int cl = wh * 32 + nt * 8 + (lane & 3) * 2;
            const int cg = kbase + cl;
            float p[4];
#pragma unroll
            for (int e = 0; e < 4; e++) {
                const int qg = (e < 2) ? qg0 : qg1;
                const int kg = cg + (e & 1);
                int dlt = qg - kg; if (dlt < 0) dlt = -dlt;
                if (dlt <= WINDOW) {
                    float E = fexp(sacc[nt][e] * 0.0025f);
                    float l = fmaf(-100.f, frcp(E + 1.f), 50.f);
                    p[e] = fexp(l);
                } else p[e] = 0.f;
            }
            psum0 += p[0] + p[1];
            psum1 += p[2] + p[3];
            *(__half2*)(smraw + oPh + (r0 * PST + cl) * 2) =
                __halves2half2(__float2half(p[0]), __float2half(p[1]));
            *(__half2*)(smraw + oPh + (r1 * PST + cl) * 2) =
                __halves2half2(__float2half(p[2]), __float2half(p[3]));
        }
        psum0 += __shfl_xor_sync(0xffffffffu, psum0, 1);
        psum0 += __shfl_xor_sync(0xffffffffu, psum0, 2);
        psum1 += __shfl_xor_sync(0xffffffffu, psum1, 1);
        psum1 += __shfl_xor_sync(0xffffffffu, psum1, 2);
        if ((lane & 3) == 0) {
            atomicAdd(&lrow[r0], psum0);
            atomicAdd(&lrow[r1], psum1);
        }

        asm volatile("cp.async.wait_group %0;" :: "n"(0) : "memory");
        __syncthreads();

        if (t + 1 < ntiles) {                 // prefetch K(t+1)
            int kb = kbase + 64;
#pragma unroll
            for (int i = 0; i < 8; i++) {
                int id = tid + i * 256;
                int row = id >> 5, ch = id & 31;
                cp16(sb + oKh + row * (DST * 2) + ch * 16, gKh + (size_t)(kb + row) * (KCOLS * 2) + ch * 16);
            }
            asm volatile("cp.async.commit_group;" ::: "memory");
        }

        // ---- O += P V (single-term) ----
#pragma unroll
        for (int kp = 0; kp < 4; kp++) {
            const uint32_t ko = kp * 32;
            uint32_t pah[4];
            ldmx4(pah, sb + oPh + ap_off + ko);
#pragma unroll
            for (int np = 0; np < 8; np++) {
                uint32_t vbh[4];
                ldmx4(vbh, sb + oVh + bv_off[np] + ko);
#pragma unroll
                for (int i = 0; i < 2; i++) {
                    const int nt = np * 2 + i, bi = i * 2;
                    mma_f16(oacc[nt], pah, vbh[bi], vbh[bi + 1]);
                }
            }
        }
        __syncthreads();

        if (t + 1 < ntiles) {                 // prefetch V(t+1)
            int kb = kbase + 64;
#pragma unroll
            for (int i = 0; i < 8; i++) {
                int id = tid + i * 256;
                int row = id >> 3, ch = id & 7;
                cp16(sb + oVh + row * (VST * 2) + ch * 16, gVh + (size_t)row * (SEQ * 2) + kb * 2 + ch * 16);
            }
            asm volatile("cp.async.commit_group;" ::: "memory");
            asm volatile("cp.async.wait_group %0;" :: "n"(1) : "memory");
        }
        __syncthreads();
    }

    // ---- normalize, write context (single fp16) ----
    const float inv0 = 1.0f / lrow[r0];
    const float inv1 = 1.0f / lrow[r1];
    const size_t row0 = (size_t)(b * SEQ + q0 + r0) * QCOLS;
    const size_t row1 = (size_t)(b * SEQ + q0 + r1) * QCOLS;
#pragma unroll
    for (int nt = 0; nt < 16; nt++) {
        const int col = h * HDIM + wh * 128 + nt * 8 + (lane & 3) * 2;
        *(__half2*)(Ch + row0 + col) =
            __halves2half2(__float2half(oacc[nt][0] * inv0),
                           __float2half(oacc[nt][1] * inv0));
        *(__half2*)(Ch + row1 + col) =
            __halves2half2(__float2half(oacc[nt][2] * inv1),
                           __float2half(oacc[nt][3] * inv1));
    }
}

// ---------------------------------------------------------------------------
// launch
// ---------------------------------------------------------------------------
extern "C" void kernel_launch(void* const* d_in, const int* in_sizes, int n_in,
                              void* d_out, int out_size)
{
    const float* hid = (const float*)d_in[0];
    const float* Wq  = (const float*)d_in[1];
    const float* Wk  = (const float*)d_in[2];
    const float* Wv  = (const float*)d_in[3];
    const float* Wo  = (const float*)d_in[4];
    float* out = (float*)d_out;

    float *Vb;
    cudaGetSymbolAddress((void**)&Vb, g_V);

    __half *Hh, *Hl, *WpH, *WotH, *Ch, *Qh, *Ql, *Kh, *VtH;
    cudaGetSymbolAddress((void**)&Hh,   g_Hh);
    cudaGetSymbolAddress((void**)&Hl,   g_Hl);
    cudaGetSymbolAddress((void**)&WpH,  g_WpH);
    cudaGetSymbolAddress((void**)&WotH, g_WotH);
    cudaGetSymbolAddress((void**)&Ch,   g_Ch);
    cudaGetSymbolAddress((void**)&Qh,   g_Qh);
    cudaGetSymbolAddress((void**)&Ql,   g_Ql);
    cudaGetSymbolAddress((void**)&Kh,   g_Kh);
    cudaGetSymbolAddress((void**)&VtH,  g_VtH);

    cudaFuncSetAttribute(gemm_mma_kernel, cudaFuncAttributeMaxDynamicSharedMemorySize,
                         GEMM_SMEM);
    cudaFuncSetAttribute(attn_tc_kernel, cudaFuncAttributeMaxDynamicSharedMemorySize,
                         ATTN_SMEM);

    rope_tables_kernel<<<(SEQ * 128 + 255) / 256, 256>>>();

    // preprocessing (Q/K cols permuted for RoPE-fused epilogue)
    split_kernel<<<(MROWS * EMBED / 4 + 255) / 256, 256>>>(hid, Hh, Hl, MROWS * EMBED / 4);
    tsplit_kernel<<<dim3(QCOLS / 32, EMBED / 32), dim3(32, 8)>>>(Wq, WpH, EMBED, QCOLS, 1, 0);
    tsplit_kernel<<<dim3(KCOLS / 32, EMBED / 32), dim3(32, 8)>>>(Wk, WpH, EMBED, KCOLS, 1, QCOLS);
    tsplit_kernel<<<dim3(KCOLS / 32, EMBED / 32), dim3(32, 8)>>>(Wv, WpH, EMBED, KCOLS, 0, QCOLS + KCOLS);
    tsplit_kernel<<<dim3(EMBED / 32, QCOLS / 32), dim3(32, 8)>>>(Wo, WotH, QCOLS, EMBED, 0, 0);

    // fused QKV projection (Q/K: A split Hh+Hl; V columns: single-term)
    gemm_mma_kernel<<<dim3((NPACK / 128) * (MROWS / 128)), 256, GEMM_SMEM>>>(
        Hh, Hl, WpH, nullptr, MROWS, NPACK, EMBED,
        1, Qh, Ql, Kh, Vb);

    // V transpose
    vtsplit_kernel<<<dim3(SEQ / 32, KCOLS / 32, BATCH), dim3(32, 8)>>>(Vb, VtH);

    // attention -> Ch single fp16
    attn_tc_kernel<<<dim3(SEQ / 64, BATCH * NH), 256, ATTN_SMEM>>>(
        Qh, Ql, Kh, VtH, Ch);

    // output projection (A single: Ch) straight into d_out
    gemm_mma_kernel<<<dim3((EMBED / 128) * (MROWS / 128)), 256, GEMM_SMEM>>>(
        Ch, nullptr, WotH, out, MROWS, EMBED, QCOLS,
        0, nullptr, nullptr, nullptr, nullptr);
}

// round 17
// speedup vs baseline: 1.9985x; 1.1305x over previous
#include <cuda_runtime.h>
#include <cuda_fp16.h>
#include <math.h>
#include <stdint.h>

// ---------------------------------------------------------------------------
// Problem constants
// ---------------------------------------------------------------------------
#define BATCH   2
#define SEQ     2048
#define EMBED   3584
#define NH      16
#define NKV     8
#define HDIM    256
#define MROWS   (BATCH*SEQ)          // 4096
#define QCOLS   (NH*HDIM)            // 4096
#define KCOLS   (NKV*HDIM)           // 2048
#define NPACK   (QCOLS + 2*KCOLS)    // 8192 packed QKV columns
#define WINDOW  1024

// ---------------------------------------------------------------------------
// Static device scratch (no cudaMalloc allowed)
// ---------------------------------------------------------------------------
__device__ float g_V  [(size_t)MROWS*KCOLS];
__device__ float g_cos[SEQ*(HDIM/2)];
__device__ float g_sin[SEQ*(HDIM/2)];

// fp16 operands
__device__ __half g_Hh [(size_t)MROWS*EMBED];
__device__ __half g_Hl [(size_t)MROWS*EMBED];
__device__ __half g_WpH[(size_t)NPACK*EMBED];    // packed Wq|Wk|Wv, transposed
__device__ __half g_WotH[(size_t)EMBED*QCOLS];   // Wo transposed
__device__ __half g_Ch [(size_t)MROWS*QCOLS];    // attention output, single fp16

// attention operands
__device__ __half g_Qh [(size_t)MROWS*QCOLS];
__device__ __half g_Ql [(size_t)MROWS*QCOLS];
__device__ __half g_Kh [(size_t)MROWS*KCOLS];    // single fp16 (B side)
__device__ __half g_VtH[(size_t)MROWS*KCOLS];    // per-batch transposed [KCOLS][SEQ]

// ---------------------------------------------------------------------------
// PTX helpers (sm_100-safe)
// ---------------------------------------------------------------------------
__device__ __forceinline__ uint32_t smem_u32(const void* p) {
    uint32_t a;
    asm("{ .reg .u64 t; cvta.to.shared.u64 t, %1; cvt.u32.u64 %0, t; }" : "=r"(a) : "l"(p));
    return a;
}
__device__ __forceinline__ void cp16(uint32_t dst, const void* src) {
    asm volatile("cp.async.cg.shared.global [%0], [%1], 16;" :: "r"(dst), "l"(src) : "memory");
}
__device__ __forceinline__ void ldmx4(uint32_t* r, uint32_t addr) {
    asm volatile("ldmatrix.sync.aligned.m8n8.x4.shared.b16 {%0,%1,%2,%3}, [%4];"
                 : "=r"(r[0]), "=r"(r[1]), "=r"(r[2]), "=r"(r[3]) : "r"(addr));
}
__device__ __forceinline__ void mma_f16(float* c, const uint32_t* a,
                                        uint32_t b0, uint32_t b1) {
    asm volatile(
        "mma.sync.aligned.m16n8k16.row.col.f32.f16.f16.f32 "
        "{%0,%1,%2,%3}, {%4,%5,%6,%7}, {%8,%9}, {%0,%1,%2,%3};"
        : "+f"(c[0]), "+f"(c[1]), "+f"(c[2]), "+f"(c[3])
        : "r"(a[0]), "r"(a[1]), "r"(a[2]), "r"(a[3]), "r"(b0), "r"(b1));
}

// FMA-pipe exp (no MUFU): e^x for |x| <= ~85, rel err ~1.5e-7
__device__ __forceinline__ float fexp(float x) {
    float y  = x * 1.4426950408889634f;
    float fm = y + 12582912.0f;
    float nf = fm - 12582912.0f;
    float f  = y - nf;
    int   sc = ((__float_as_int(fm) - 0x4B400000) + 127) << 23;
    float t  = f * 0.6931471805599453f;
    float p  = 1.0f + t*(1.0f + t*(0.5f + t*(0.16666667f +
               t*(0.041666667f + t*(0.008333334f + t*0.0013888889f)))));
    return p * __int_as_float(sc);
}
// FMA-pipe reciprocal (bit-hack + 3 Newton)
__device__ __forceinline__ float frcp(float d) {
    float r = __int_as_float(0x7EF311C3 - __float_as_int(d));
    r = r * (2.0f - d * r);
    r = r * (2.0f - d * r);
    r = r * (2.0f - d * r);
    return r;
}

// ---------------------------------------------------------------------------
// fp32 -> fp16 hi/lo split (vectorized)
// ---------------------------------------------------------------------------
__global__ void split_kernel(const float* __restrict__ in,
                             __half* __restrict__ hi,
                             __half* __restrict__ lo, int n4)
{
    int i = blockIdx.x * 256 + threadIdx.x;
    if (i >= n4) return;
    float4 v = ((const float4*)in)[i];
    __half h0 = __float2half(v.x);
    __half h1 = __float2half(v.y);
    __half h2 = __float2half(v.z);
    __half h3 = __float2half(v.w);
    __half l0 = __float2half(v.x - __half2float(h0));
    __half l1 = __float2half(v.y - __half2float(h1));
    __half l2 = __float2half(v.z - __half2float(h2));
    __half l3 = __float2half(v.w - __half2float(h3));
    ((__half2*)hi)[2*i]   = __halves2half2(h0, h1);
    ((__half2*)hi)[2*i+1] = __halves2half2(h2, h3);
    ((__half2*)lo)[2*i]   = __halves2half2(l0, l1);
    ((__half2*)lo)[2*i+1] = __halves2half2(l2, l3);
}

// ---------------------------------------------------------------------------
// Transpose (+optional RoPE-pair perm): W [K,N] fp32 -> Th [rowoff+perm(n)][K] fp16
// ---------------------------------------------------------------------------
__global__ void tsplit_kernel(const float* __restrict__ W,
                              __half* __restrict__ Th, int K, int N,
                              int perm, int rowoff)
{
    __shared__ float t[32][33];
    int n0 = blockIdx.x * 32, k0 = blockIdx.y * 32;
    int tx = threadIdx.x, ty = threadIdx.y;
#pragma unroll
    for (int i = 0; i < 32; i += 8)
        t[ty + i][tx] = W[(size_t)(k0 + ty + i) * N + n0 + tx];
    __syncthreads();
#pragma unroll
    for (int i = 0; i < 32; i += 8) {
        float v = t[tx][ty + i];
        int n = n0 + ty + i;
        int nb = n & 255;
        int np = perm ? ((n & ~255) + ((nb < 128) ? (nb << 1) : (((nb - 128) << 1) | 1)))
                      : n;
        Th[(size_t)(rowoff + np) * K + k0 + tx] = __float2half(v);
    }
}

// ---------------------------------------------------------------------------
// V transpose per batch: g_V [b*SEQ+s][KCOLS] -> Vt [b][KCOLS][SEQ] fp16
// ---------------------------------------------------------------------------
__global__ void vtsplit_kernel(const float* __restrict__ V,
                               __half* __restrict__ Th)
{
    __shared__ float t[32][33];
    int s0 = blockIdx.x * 32, c0 = blockIdx.y * 32, b = blockIdx.z;
    int tx = threadIdx.x, ty = threadIdx.y;
#pragma unroll
    for (int i = 0; i < 32; i += 8)
        t[ty + i][tx] = V[((size_t)b * SEQ + s0 + ty + i) * KCOLS + c0 + tx];
    __syncthreads();
#pragma unroll
    for (int i = 0; i < 32; i += 8) {
        float v = t[tx][ty + i];
        size_t o = ((size_t)b * KCOLS + c0 + ty + i) * SEQ + s0 + tx;
        Th[o] = __float2half(v);
    }
}

// ---------------------------------------------------------------------------
// RoPE tables (double precision)
// ---------------------------------------------------------------------------
__global__ void rope_tables_kernel()
{
    int idx = blockIdx.x * 256 + threadIdx.x;
    if (idx >= SEQ * (HDIM / 2)) return;
    int i = idx & 127;
    int pos = idx >> 7;
    double invf = pow(10000.0, -(double)(2 * i) / (double)HDIM);
    double ang = (double)pos * invf;
    g_cos[idx] = (float)cos(ang);
    g_sin[idx] = (float)sin(ang);
}

// ---------------------------------------------------------------------------
// mma.sync fp16 GEMM: C = (Ah[+Al])[M,K] @ Bh[N,K]^T, 3-stage pipeline,
// 2 CTAs/SM, supertile rasterization. Al==nullptr -> single-term A.
// mode 0: plain fp32 C. mode 1: fused QKV (RoPE epilogue Q->h/l, K->single,
// V segment -> Vb fp32). Precision policy in fused mode: only the K segment
// uses the A-lo term (logit path); Q and V segments run single-term.
// ---------------------------------------------------------------------------
#define GKC       32
#define GSTRIDE   40
#define GTILE_B   (128*GSTRIDE*2)    // 10240 B per tile
#define GSTAGE_B  (3*GTILE_B)        // Ah, Al, Bh = 30720 B
#define GEMM_SMEM (3*GSTAGE_B)       // 92160 B -> 2 CTAs/SM
#define GSW       16

__device__ __forceinline__ void fill_stage(uint32_t stb,
                                           const __half* Ah0,
                                           const __half* Al0,
                                           const __half* Bh0,
                                           int K, int tid)
{
    const __half* srcs[3] = {Ah0, Al0, Bh0};
#pragma unroll
    for (int t = 0; t < 3; t++) {
        if (!srcs[t]) continue;
        uint32_t tb = stb + t * GTILE_B;
        const char* s = (const char*)srcs[t];
#pragma unroll
        for (int i = 0; i < 2; i++) {
            int id = tid + i * 256;
            int row = id >> 2, ch = id & 3;
            cp16(tb + row * (GSTRIDE * 2) + ch * 16,
                 s + (size_t)row * K * 2 + ch * 16);
        }
    }
    asm volatile("cp.async.commit_group;" ::: "memory");
}

__global__ void __launch_bounds__(256, 2)
gemm_mma_kernel(const __half* __restrict__ Ah,
                const __half* __restrict__ Al,
                const __half* __restrict__ Bh,
                float* __restrict__ C, int M, int N, int K,
                int fused,
                __half* __restrict__ Qh, __half* __restrict__ Ql,
                __half* __restrict__ Kh,
                float* __restrict__ Vb)
{
    extern __shared__ char gsm[];
    const uint32_t sbase = smem_u32(gsm);
    const int tid = threadIdx.x;
    const int wid = tid >> 5, lane = tid & 31;
    const int wm = wid & 1, wn = wid >> 1;

    // supertile rasterization
    const int Mt = M >> 7, Ntl = N >> 7;
    int mtile, ntile;
    {
        const int bid = blockIdx.x;
        const int per = GSW * Mt;
        const int fullcols = Ntl / GSW;
        if (bid < fullcols * per) {
            const int col = bid / per;
            const int r = bid % per;
            mtile = r / GSW;
            ntile = col * GSW + r % GSW;
        } else {
            const int r = bid - fullcols * per;
            const int wdt = Ntl - fullcols * GSW;
            mtile = r / wdt;
            ntile = fullcols * GSW + r % wdt;
        }
    }
    const int m0 = mtile * 128, n0 = ntile * 128;

    // Only the K-projection segment keeps the A-lo correction term: K errors
    // feed logits (amplified ~2x by softmax spread). Q gets its exactness
    // from the attention-side Qh/Ql split; V's error path has unit gain.
    const bool useAl = (Al != nullptr) &&
                       (!fused || (n0 >= QCOLS && n0 < QCOLS + KCOLS));

    uint32_t a_off[4], b_off[2];
#pragma unroll
    for (int mt = 0; mt < 4; mt++)
        a_off[mt] = ((wm * 64 + mt * 16 + (lane & 15)) * GSTRIDE
                     + (lane >> 4) * 8) * 2;
#pragma unroll
    for (int np = 0; np < 2; np++)
        b_off[np] = ((wn * 32 + np * 16 + (lane & 7) + ((lane >> 4) & 1) * 8) * GSTRIDE
                     + ((lane >> 3) & 1) * 8) * 2;

    const __half* Ah0 = Ah + (size_t)m0 * K;
    const __half* Al0 = useAl ? (Al + (size_t)m0 * K) : nullptr;
    const __half* Bh0 = Bh + (size_t)n0 * K;

    float acc[4][4][4];
#pragma unroll
    for (int mt = 0; mt < 4; mt++)
#pragma unroll
        for (int nt = 0; nt < 4; nt++)
#pragma unroll
            for (int r = 0; r < 4; r++) acc[mt][nt][r] = 0.f;

    const int NC = K / GKC;

#pragma unroll
    for (int c = 0; c < 3; c++)
        fill_stage(sbase + c * GSTAGE_B, Ah0 + c * GKC,
                   Al0 ? Al0 + c * GKC : nullptr,
                   Bh0 + c * GKC, K, tid);

    for (int c = 0; c < NC; c++) {
        const uint32_t stb = sbase + (c % 3) * GSTAGE_B;
        asm volatile("cp.async.wait_group %0;" :: "n"(2) : "memory");
        __syncthreads();

#pragma unroll
        for (int ks = 0; ks < 2; ks++) {
            const uint32_t ko = ks * 32;
            uint32_t ax[4][4], bx[2][4];

#pragma unroll
            for (int mt = 0; mt < 4; mt++) ldmx4(ax[mt], stb + 0 * GTILE_B + a_off[mt] + ko);
#pragma unroll
            for (int np = 0; np < 2; np++) ldmx4(bx[np], stb + 2 * GTILE_B + b_off[np] + ko);

            // term 1: Ah * B
#pragma unroll
            for (int mt = 0; mt < 4; mt++)
#pragma unroll
                for (int nt = 0; nt < 4; nt++) {
                    const int np = nt >> 1, bi = (nt & 1) * 2;
                    mma_f16(acc[mt][nt], ax[mt], bx[np][bi], bx[np][bi + 1]);
                }

            // term 2: Al * B (only when A is split)
            if (Al0) {
#pragma unroll
                for (int mt = 0; mt < 4; mt++) ldmx4(ax[mt], stb + 1 * GTILE_B + a_off[mt] + ko);
#pragma unroll
                for (int mt = 0; mt < 4; mt++)
#pragma unroll
                    for (int nt = 0; nt < 4; nt++) {
                        const int np = nt >> 1, bi = (nt & 1) * 2;
                        mma_f16(acc[mt][nt], ax[mt], bx[np][bi], bx[np][bi + 1]);
                    }
            }
        }

        __syncthreads();
        const int cn = c + 3;
        if (cn < NC)
            fill_stage(stb, Ah0 + cn * GKC,
                       Al0 ? Al0 + cn * GKC : nullptr,
                       Bh0 + cn * GKC, K, tid);
    }

    const int rr = lane >> 2, cc = (lane & 3) * 2;

    if (!fused) {
#pragma unroll
        for (int mt = 0; mt < 4; mt++) {
            const size_t mA = (size_t)(m0 + wm * 64 + mt * 16 + rr);
#pragma unroll
            for (int nt = 0; nt < 4; nt++) {
                const int n = n0 + wn * 32 + nt * 8 + cc;
                *(float2*)(C + mA * N + n) =
                    make_float2(acc[mt][nt][0], acc[mt][nt][1]);
                *(float2*)(C + (mA + 8) * N + n) =
                    make_float2(acc[mt][nt][2], acc[mt][nt][3]);
            }
        }
        return;
    }

    if (n0 >= QCOLS + KCOLS) {
        // V segment: fp32 into Vb (stride KCOLS)
#pragma unroll
        for (int mt = 0; mt < 4; mt++) {
            const size_t mA = (size_t)(m0 + wm * 64 + mt * 16 + rr);
#pragma unroll
            for (int nt = 0; nt < 4; nt++) {
                const int n = (n0 - (QCOLS + KCOLS)) + wn * 32 + nt * 8 + cc;
                *(float2*)(Vb + mA * KCOLS + n) =
                    make_float2(acc[mt][nt][0], acc[mt][nt][1]);
                *(float2*)(Vb + (mA + 8) * KCOLS + n) =
                    make_float2(acc[mt][nt][2], acc[mt][nt][3]);
            }
        }
        return;
    }

    // Q or K segment: RoPE; Q -> h/l split, K -> single fp16
    const int isQ = (n0 < QCOLS);
    const int xs = isQ ? QCOLS : KCOLS;
    const int segbase = isQ ? 0 : QCOLS;

#pragma unroll
    for (int mt = 0; mt < 4; mt++) {
        const int mA = m0 + wm * 64 + mt * 16 + rr;
#pragma unroll
        for (int nt = 0; nt < 4; nt++) {
            const int colp = (n0 - segbase) + wn * 32 + nt * 8 + cc; // even
            const int head = colp >> 8;
            const int i    = (colp & 255) >> 1;
            const int ca   = head * 256 + i;
            const int cb   = ca + 128;
#pragma unroll
            for (int rh = 0; rh < 2; rh++) {
                const int m   = mA + rh * 8;
                const int pos = m & (SEQ - 1);
                const float co = g_cos[pos * 128 + i];
                const float si = g_sin[pos * 128 + i];
                const float x1 = acc[mt][nt][rh * 2 + 0];
                const float x2 = acc[mt][nt][rh * 2 + 1];
                const float y1 = x1 * co - x2 * si;
                const float y2 = x2 * co + x1 * si;
                const size_t rb = (size_t)m * xs;
                if (isQ) {
                    const __half h1 = __float2half(y1);
                    const __half h2 = __float2half(y2);
                    Qh[rb + ca] = h1;
                    Qh[rb + cb] = h2;
                    Ql[rb + ca] = __float2half(y1 - __half2float(h1));
                    Ql[rb + cb] = __float2half(y2 - __half2float(h2));
                } else {
                    Kh[rb + ca] = __float2half(y1);
                    Kh[rb + cb] = __float2half(y2);
                }
            }
        }
    }
}

// ---------------------------------------------------------------------------
// Tensor-core flash attention: S = (Qh+Ql)K^T (2 terms), O += P V (P single),
// no-max softmax (|logit| <= 50), FMA-pipe exp/rcp. Output: single fp16 C.
// ---------------------------------------------------------------------------
#define DST 264   // Q/K smem row stride (fp16)
#define VST 72
#define PST 72
#define oQh 0
#define oQl 33792
#define oKh 67584
#define oVh 101376
#define oPh 138240
#define oLrow 147456
#define ATTN_SMEM (147456 + 256)

__global__ void __launch_bounds__(256, 1)
attn_tc_kernel(const __half* __restrict__ Qh, const __half* __restrict__ Ql,
               const __half* __restrict__ Kh,
               const __half* __restrict__ Vth,
               __half* __restrict__ Ch)
{
    extern __shared__ char smraw[];
    const uint32_t sb = smem_u32(smraw);
    float* lrow = (float*)(smraw + oLrow);

    const int tid = threadIdx.x;
    const int wid = tid >> 5, lane = tid & 31;
    const int wq = wid & 3, wh = wid >> 2;
    const int b  = blockIdx.y >> 4;
    const int h  = blockIdx.y & 15;
    const int kvh = h >> 1;
    const int q0 = blockIdx.x * 64;

    const char* gQh = (const char*)(Qh + ((size_t)(b * SEQ + q0)) * QCOLS + h * HDIM);
    const char* gQl = (const char*)(Ql + ((size_t)(b * SEQ + q0)) * QCOLS + h * HDIM);
    const char* gKh = (const char*)(Kh + ((size_t)(b * SEQ)) * KCOLS + kvh * HDIM);
    const char* gVh = (const char*)(Vth + ((size_t)(b * KCOLS + kvh * HDIM)) * SEQ);

    if (tid < 64) lrow[tid] = 0.f;

    int klo = q0 - WINDOW;       if (klo < 0) klo = 0;
    int khi = q0 + 64 + WINDOW;  if (khi > SEQ) khi = SEQ;
    const int kt0 = klo >> 6;
    const int ntiles = (khi >> 6) - kt0;

#pragma unroll
    for (int i = 0; i < 8; i++) {
        int id = tid + i * 256;
        int row = id >> 5, ch = id & 31;
        cp16(sb + oQh + row * (DST * 2) + ch * 16, gQh + (size_t)row * (QCOLS * 2) + ch * 16);
        cp16(sb + oQl + row * (DST * 2) + ch * 16, gQl + (size_t)row * (QCOLS * 2) + ch * 16);
    }
    {
        int kb = kt0 * 64;
#pragma unroll
        for (int i = 0; i < 8; i++) {
            int id = tid + i * 256;
            int row = id >> 5, ch = id & 31;
            cp16(sb + oKh + row * (DST * 2) + ch * 16, gKh + (size_t)(kb + row) * (KCOLS * 2) + ch * 16);
        }
        asm volatile("cp.async.commit_group;" ::: "memory");
#pragma unroll
        for (int i = 0; i < 8; i++) {
            int id = tid + i * 256;
            int row = id >> 3, ch = id & 7;
            cp16(sb + oVh + row * (VST * 2) + ch * 16, gVh + (size_t)row * (SEQ * 2) + kb * 2 + ch * 16);
        }
        asm volatile("cp.async.commit_group;" ::: "memory");
    }
    asm volatile("cp.async.wait_group %0;" :: "n"(1) : "memory");
    __syncthreads();

    const uint32_t a_off = ((wq * 16 + (lane & 15)) * DST + (lane >> 4) * 8) * 2;
    uint32_t bs_off[2];
#pragma unroll
    for (int np = 0; np < 2; np++)
        bs_off[np] = ((wh * 32 + np * 16 + (lane & 7) + ((lane >> 4) & 1) * 8) * DST
                      + ((lane >> 3) & 1) * 8) * 2;
    const uint32_t ap_off = ((wq * 16 + (lane & 15)) * PST + (lane >> 4) * 8) * 2;
    uint32_t bv_off[8];
#pragma unroll
    for (int np = 0; np < 8; np++)
        bv_off[np] = ((wh * 128 + np * 16 + (lane & 7) + ((lane >> 4) & 1) * 8) * VST
                      + ((lane >> 3) & 1) * 8) * 2;

    float oacc[16][4];
#pragma unroll
    for (int nt = 0; nt < 16; nt++)
#pragma unroll
        for (int r = 0; r < 4; r++) oacc[nt][r] = 0.f;

    const int r0 = wq * 16 + (lane >> 2), r1 = r0 + 8;
    const int qg0 = q0 + r0, qg1 = q0 + r1;

    for (int t = 0; t < ntiles; t++) {
        const int kbase = (kt0 + t) * 64;

        // ---- S = (Qh+Ql) K^T ----
        float sacc[4][4];
#pragma unroll
        for (int nt = 0; nt < 4; nt++)
#pragma unroll
            for (int r = 0; r < 4; r++) sacc[nt][r] = 0.f;

#pragma unroll 4
        for (int ks = 0; ks < 16; ks++) {
            const uint32_t ko = ks * 32;
            uint32_t qhf[4], qlf[4], khf[2][4];
            ldmx4(qhf, sb + oQh + a_off + ko);
            ldmx4(qlf, sb + oQl + a_off + ko);
#pragma unroll
            for (int np = 0; np < 2; np++)
                ldmx4(khf[np], sb + oKh + bs_off[np] + ko);
#pragma unroll
            for (int nt = 0; nt < 4; nt++) {
                const int np = nt >> 1, bi = (nt & 1) * 2;
                mma_f16(sacc[nt], qhf, khf[np][bi], khf[np][bi + 1]);
                mma_f16(sacc[nt], qlf, khf[np][bi], khf[np][bi + 1]);
            }
        }

        // ---- soft-cap + window mask + exp, write P (single fp16) ----
        float psum0 = 0.f, psum1 = 0.f;
#pragma unroll
        for (int nt = 0; nt < 4; nt++) {
            const int cl = wh * 32 + nt * 8 + (lane & 3) * 2;
            const int cg = kbase + cl;
            float p[4];
#pragma unroll
            for (int e = 0; e < 4; e++) {
                const int qg = (e < 2) ? qg0 : qg1;
                const int kg = cg + (e & 1);
                int dlt = qg - kg; if (dlt < 0) dlt = -dlt;
                if (dlt <= WINDOW) {
                    float E = fexp(sacc[nt][e] * 0.0025f);
                    float l = fmaf(-100.f, frcp(E + 1.f), 50.f);
                    p[e] = fexp(l);
                } else p[e] = 0.f;
            }
            psum0 += p[0] + p[1];
            psum1 += p[2] + p[3];
            *(__half2*)(smraw + oPh + (r0 * PST + cl) * 2) =
                __halves2half2(__float2half(p[0]), __float2half(p[1]));
            *(__half2*)(smraw + oPh + (r1 * PST + cl) * 2) =
                __halves2half2(__float2half(p[2]), __float2half(p[3]));
        }
        psum0 += __shfl_xor_sync(0xffffffffu, psum0, 1);
        psum0 += __shfl_xor_sync(0xffffffffu, psum0, 2);
        psum1 += __shfl_xor_sync(0xffffffffu, psum1, 1);
        psum1 += __shfl_xor_sync(0xffffffffu, psum1, 2);
        if ((lane & 3) == 0) {
            atomicAdd(&lrow[r0], psum0);
            atomicAdd(&lrow[r1], psum1);
        }

        asm volatile("cp.async.wait_group %0;" :: "n"(0) : "memory");
        __syncthreads();

        if (t + 1 < ntiles) {                 // prefetch K(t+1)
            int kb = kbase + 64;
#pragma unroll
            for (int i = 0; i < 8; i++) {
                int id = tid + i * 256;
                int row = id >> 5, ch = id & 31;
                cp16(sb + oKh + row * (DST * 2) + ch * 16, gKh + (size_t)(kb + row) * (KCOLS * 2) + ch * 16);
            }
            asm volatile("cp.async.commit_group;" ::: "memory");
        }

        // ---- O += P V (single-term) ----
#pragma unroll
        for (int kp = 0; kp < 4; kp++) {
            const uint32_t ko = kp * 32;
            uint32_t pah[4];
            ldmx4(pah, sb + oPh + ap_off + ko);
#pragma unroll
            for (int np = 0; np < 8; np++) {
                uint32_t vbh[4];
                ldmx4(vbh, sb + oVh + bv_off[np] + ko);
#pragma unroll
                for (int i = 0; i < 2; i++) {
                    const int nt = np * 2 + i, bi = i * 2;
                    mma_f16(oacc[nt], pah, vbh[bi], vbh[bi + 1]);
                }
            }
        }
        __syncthreads();

        if (t + 1 < ntiles) {                 // prefetch V(t+1)
            int kb = kbase + 64;
#pragma unroll
            for (int i = 0; i < 8; i++) {
                int id = tid + i * 256;
                int row = id >> 3, ch = id & 7;
                cp16(sb + oVh + row * (VST * 2) + ch * 16, gVh + (size_t)row * (SEQ * 2) + kb * 2 + ch * 16);
            }
            asm volatile("cp.async.commit_group;" ::: "memory");
            asm volatile("cp.async.wait_group %0;" :: "n"(1) : "memory");
        }
        __syncthreads();
    }

    // ---- normalize, write context (single fp16) ----
    const float inv0 = 1.0f / lrow[r0];
    const float inv1 = 1.0f / lrow[r1];
    const size_t row0 = (size_t)(b * SEQ + q0 + r0) * QCOLS;
    const size_t row1 = (size_t)(b * SEQ + q0 + r1) * QCOLS;
#pragma unroll
    for (int nt = 0; nt < 16; nt++) {
        const int col = h * HDIM + wh * 128 + nt * 8 + (lane & 3) * 2;
        *(__half2*)(Ch + row0 + col) =
            __halves2half2(__float2half(oacc[nt][0] * inv0),
                           __float2half(oacc[nt][1] * inv0));
        *(__half2*)(Ch + row1 + col) =
            __halves2half2(__float2half(oacc[nt][2] * inv1),
                           __float2half(oacc[nt][3] * inv1));
    }
}

// ---------------------------------------------------------------------------
// launch
// ---------------------------------------------------------------------------
extern "C" void kernel_launch(void* const* d_in, const int* in_sizes, int n_in,
                              void* d_out, int out_size)
{
    const float* hid = (const float*)d_in[0];
    const float* Wq  = (const float*)d_in[1];
    const float* Wk  = (const float*)d_in[2];
    const float* Wv  = (const float*)d_in[3];
    const float* Wo  = (const float*)d_in[4];
    float* out = (float*)d_out;

    float *Vb;
    cudaGetSymbolAddress((void**)&Vb, g_V);

    __half *Hh, *Hl, *WpH, *WotH, *Ch, *Qh, *Ql, *Kh, *VtH;
    cudaGetSymbolAddress((void**)&Hh,   g_Hh);
    cudaGetSymbolAddress((void**)&Hl,   g_Hl);
    cudaGetSymbolAddress((void**)&WpH,  g_WpH);
    cudaGetSymbolAddress((void**)&WotH, g_WotH);
    cudaGetSymbolAddress((void**)&Ch,   g_Ch);
    cudaGetSymbolAddress((void**)&Qh,   g_Qh);
    cudaGetSymbolAddress((void**)&Ql,   g_Ql);
    cudaGetSymbolAddress((void**)&Kh,   g_Kh);
    cudaGetSymbolAddress((void**)&VtH,  g_VtH);

    cudaFuncSetAttribute(gemm_mma_kernel, cudaFuncAttributeMaxDynamicSharedMemorySize,
                         GEMM_SMEM);
    cudaFuncSetAttribute(attn_tc_kernel, cudaFuncAttributeMaxDynamicSharedMemorySize,
                         ATTN_SMEM);

    rope_tables_kernel<<<(SEQ * 128 + 255) / 256, 256>>>();

    // preprocessing (Q/K cols permuted for RoPE-fused epilogue)
    split_kernel<<<(MROWS * EMBED / 4 + 255) / 256, 256>>>(hid, Hh, Hl, MROWS * EMBED / 4);
    tsplit_kernel<<<dim3(QCOLS / 32, EMBED / 32), dim3(32, 8)>>>(Wq, WpH, EMBED, QCOLS, 1, 0);
    tsplit_kernel<<<dim3(KCOLS / 32, EMBED / 32), dim3(32, 8)>>>(Wk, WpH, EMBED, KCOLS, 1, QCOLS);
    tsplit_kernel<<<dim3(KCOLS / 32, EMBED / 32), dim3(32, 8)>>>(Wv, WpH, EMBED, KCOLS, 0, QCOLS + KCOLS);
    tsplit_kernel<<<dim3(EMBED / 32, QCOLS / 32), dim3(32, 8)>>>(Wo, WotH, QCOLS, EMBED, 0, 0);

    // fused QKV projection (K segment: A split Hh+Hl; Q and V: single-term)
    gemm_mma_kernel<<<dim3((NPACK / 128) * (MROWS / 128)), 256, GEMM_SMEM>>>(
        Hh, Hl, WpH, nullptr, MROWS, NPACK, EMBED,
        1, Qh, Ql, Kh, Vb);

    // V transpose
    vtsplit_kernel<<<dim3(SEQ / 32, KCOLS / 32, BATCH), dim3(32, 8)>>>(Vb, VtH);

    // attention -> Ch single fp16
    attn_tc_kernel<<<dim3(SEQ / 64, BATCH * NH), 256, ATTN_SMEM>>>(
        Qh, Ql, Kh, VtH, Ch);

    // output projection (A single: Ch) straight into d_out
    gemm_mma_kernel<<<dim3((EMBED / 128) * (MROWS / 128)), 256, GEMM_SMEM>>>(
        Ch, nullptr, WotH, out, MROWS, EMBED, QCOLS,
        0, nullptr, nullptr, nullptr, nullptr);
}